// round 8
// baseline (speedup 1.0000x reference)
#include <cuda_runtime.h>
#include <cuda_bf16.h>
#include <cstdint>

typedef __nv_bfloat16 bf16;

#define S_  2048
#define B_  4
#define D_  256
#define NH_ 4
#define K_  1024
#define FF_ 1024
#define SB_ (S_*B_)
#define ZB_ (NH_*B_)

// ---------------- scratch ----------------
static __device__ __align__(16) bf16  g_wqh[(size_t)NH_*SB_*K_];   // 64 MB
static __device__ __align__(16) bf16  g_wkh[(size_t)NH_*SB_*K_];   // 64 MB
static __device__ __align__(16) bf16  g_P  [(size_t)ZB_*S_*S_];    // 128 MB exp(dot) bf16
static __device__ float g_P0 [ZB_*S_];                             // exact row q=0
static __device__ float g_rowsum[ZB_*S_];
static __device__ float g_inv   [ZB_*S_];
static __device__ float g_colsum[ZB_*S_];
static __device__ float g_aff0  [ZB_*S_];
static __device__ float g_ctx[ZB_*D_];
static __device__ float g_xh [ZB_*D_];
static __device__ float g_src2[B_*D_];
static __device__ __align__(16) float g_x  [SB_*D_];
static __device__ __align__(16) float g_ff [SB_*D_];
// split-bf16 FFN operands:  A' = [hi|hi|lo],  B' = [hi|lo|hi]
static __device__ __align__(16) bf16 g_xs  [(size_t)SB_*3*D_];
static __device__ __align__(16) bf16 g_h1s [(size_t)SB_*3*FF_];
static __device__ __align__(16) bf16 g_l1ws[(size_t)FF_*3*D_];
static __device__ __align__(16) bf16 g_l2ws[(size_t)D_*3*FF_];
// bf16 copies of inputs (attention path)
static __device__ __align__(16) bf16 g_srcb[SB_*D_];
static __device__ __align__(16) bf16 g_memb[SB_*D_];
static __device__ __align__(16) bf16 g_WKb [NH_*K_*D_];
static __device__ __align__(16) bf16 g_WQb [NH_*K_*D_];

// ---------------- small helpers ----------------
__device__ __forceinline__ float blk_sum(float v, float* red, int nw) {
#pragma unroll
    for (int o = 16; o > 0; o >>= 1) v += __shfl_xor_sync(0xffffffffu, v, o);
    int w = threadIdx.x >> 5;
    if ((threadIdx.x & 31) == 0) red[w] = v;
    __syncthreads();
    float s = 0.f;
    for (int i = 0; i < nw; i++) s += red[i];
    __syncthreads();
    return s;
}
__device__ __forceinline__ float ln256(float v, float g, float b, float* red) {
    float mean = blk_sum(v, red, 8) * (1.f/256.f);
    float dv = v - mean;
    float var = blk_sum(dv*dv, red, 8) * (1.f/256.f);
    return dv * rsqrtf(var + 1e-5f) * g + b;
}
__device__ __forceinline__ unsigned sa(const void* p) {
    return (unsigned)__cvta_generic_to_shared(p);
}
// exp(x) for x in [-1.05, 1.05]: degree-9 Taylor, rel err < 3e-6, all FMA-pipe
__device__ __forceinline__ float expp(float x) {
    float r = 2.7557319e-6f;
    r = fmaf(r, x, 2.4801587e-5f);
    r = fmaf(r, x, 1.9841270e-4f);
    r = fmaf(r, x, 1.3888889e-3f);
    r = fmaf(r, x, 8.3333333e-3f);
    r = fmaf(r, x, 4.1666667e-2f);
    r = fmaf(r, x, 1.6666667e-1f);
    r = fmaf(r, x, 0.5f);
    r = fmaf(r, x, 1.0f);
    r = fmaf(r, x, 1.0f);
    return r;
}

// ---------------- bf16 HMMA GEMM core (software-pipelined) ----------------
// C[M,N] = epi(A[M,Kd] @ B[N,Kd]^T), bf16 K-contiguous, fp32 accum.
// Block 128x128, BK=32, 256 threads = 8 warps (warp tile 64x32).
// Per K-chunk: hoist ALL ldmatrix (both k-halves) up front, then issue the
// next-next chunk's cp.async, then run 32 back-to-back HMMAs.
// EP: 0 bf16 raw, 1 exp(poly)->bf16 P + f32 row0 + rowsum atomics,
//     2 relu+bias -> split triple bf16, 3 bias -> f32
template<int EP>
__device__ __forceinline__ void mma_core(
    const bf16* __restrict__ A, int lda,
    const bf16* __restrict__ Bw, int ldb,
    int Kd, int m0, int n0,
    float* __restrict__ outF, bf16* __restrict__ outH, int ldc,
    const float* __restrict__ bias, float* __restrict__ rowsum, float* __restrict__ p0)
{
    __shared__ __align__(16) bf16 As[2][128][40];
    __shared__ __align__(16) bf16 Bs[2][128][40];

    const int tid  = threadIdx.x;
    const int lane = tid & 31;
    const int wid  = tid >> 5;
    const int wm0  = (wid & 1) * 64;
    const int wn0  = (wid >> 1) * 32;

    const int c0 = tid, c1 = tid + 256;
    const int ar0 = c0 >> 2, ak0 = (c0 & 3) * 8;
    const int ar1 = c1 >> 2, ak1 = (c1 & 3) * 8;

    float acc[4][4][4];
#pragma unroll
    for (int i = 0; i < 4; i++)
#pragma unroll
        for (int j = 0; j < 4; j++)
#pragma unroll
            for (int k = 0; k < 4; k++) acc[i][j][k] = 0.f;

    const int nK = Kd >> 5;

    auto issue_load = [&](int kb, int st) {
        int ko = kb * 32;
        const bf16* a0 = A  + (size_t)(m0 + ar0) * lda + ko + ak0;
        const bf16* a1 = A  + (size_t)(m0 + ar1) * lda + ko + ak1;
        const bf16* b0 = Bw + (size_t)(n0 + ar0) * ldb + ko + ak0;
        const bf16* b1 = Bw + (size_t)(n0 + ar1) * ldb + ko + ak1;
        asm volatile("cp.async.cg.shared.global [%0],[%1],16;\n"::"r"(sa(&As[st][ar0][ak0])),"l"(a0));
        asm volatile("cp.async.cg.shared.global [%0],[%1],16;\n"::"r"(sa(&As[st][ar1][ak1])),"l"(a1));
        asm volatile("cp.async.cg.shared.global [%0],[%1],16;\n"::"r"(sa(&Bs[st][ar0][ak0])),"l"(b0));
        asm volatile("cp.async.cg.shared.global [%0],[%1],16;\n"::"r"(sa(&Bs[st][ar1][ak1])),"l"(b1));
        asm volatile("cp.async.commit_group;\n");
    };

    issue_load(0, 0);
    if (nK > 1) issue_load(1, 1);

    for (int kb = 0; kb < nK; kb++) {
        if (kb + 1 < nK) asm volatile("cp.async.wait_group 1;\n" ::: "memory");
        else             asm volatile("cp.async.wait_group 0;\n" ::: "memory");
        __syncthreads();
        int st = kb & 1;

        // ---- hoisted fragment loads for BOTH k-halves ----
        unsigned a[2][4][4];
        unsigned bfr[2][4][2];
#pragma unroll
        for (int ks = 0; ks < 2; ks++) {
#pragma unroll
            for (int mt = 0; mt < 4; mt++) {
                unsigned ad = sa(&As[st][wm0 + mt*16 + (lane & 15)][ks*16 + (lane >> 4)*8]);
                asm volatile("ldmatrix.sync.aligned.m8n8.x4.shared.b16 {%0,%1,%2,%3},[%4];\n"
                    : "=r"(a[ks][mt][0]), "=r"(a[ks][mt][1]), "=r"(a[ks][mt][2]), "=r"(a[ks][mt][3]) : "r"(ad));
            }
#pragma unroll
            for (int bp = 0; bp < 2; bp++) {
                unsigned r0, r1, r2, r3;
                unsigned ad = sa(&Bs[st][wn0 + bp*16 + (lane & 15)][ks*16 + (lane >> 4)*8]);
                asm volatile("ldmatrix.sync.aligned.m8n8.x4.shared.b16 {%0,%1,%2,%3},[%4];\n"
                    : "=r"(r0), "=r"(r1), "=r"(r2), "=r"(r3) : "r"(ad));
                bfr[ks][bp*2  ][0] = r0; bfr[ks][bp*2  ][1] = r2;
                bfr[ks][bp*2+1][0] = r1; bfr[ks][bp*2+1][1] = r3;
            }
        }
        __syncthreads();          // all warps done reading this stage
        if (kb + 2 < nK) issue_load(kb + 2, st);

        // ---- 32 back-to-back HMMAs ----
#pragma unroll
        for (int ks = 0; ks < 2; ks++)
#pragma unroll
            for (int mt = 0; mt < 4; mt++)
#pragma unroll
                for (int nt = 0; nt < 4; nt++) {
                    asm volatile(
                        "mma.sync.aligned.m16n8k16.row.col.f32.bf16.bf16.f32 "
                        "{%0,%1,%2,%3},{%4,%5,%6,%7},{%8,%9},{%0,%1,%2,%3};\n"
                        : "+f"(acc[mt][nt][0]), "+f"(acc[mt][nt][1]),
                          "+f"(acc[mt][nt][2]), "+f"(acc[mt][nt][3])
                        : "r"(a[ks][mt][0]), "r"(a[ks][mt][1]), "r"(a[ks][mt][2]), "r"(a[ks][mt][3]),
                          "r"(bfr[ks][nt][0]), "r"(bfr[ks][nt][1]));
                }
    }

    // ---------------- epilogue ----------------
    const int er = lane >> 2;
    const int ec = (lane & 3) * 2;
#pragma unroll
    for (int mt = 0; mt < 4; mt++) {
        float rsum0 = 0.f, rsum1 = 0.f;
#pragma unroll
        for (int nt = 0; nt < 4; nt++) {
            int m = m0 + wm0 + mt*16 + er;
            int n = n0 + wn0 + nt*8 + ec;
            float v0 = acc[mt][nt][0], v1 = acc[mt][nt][1];
            float v2 = acc[mt][nt][2], v3 = acc[mt][nt][3];
            if (EP == 1) {
                v0 = expp(v0); v1 = expp(v1); v2 = expp(v2); v3 = expp(v3);
                rsum0 += v0 + v1; rsum1 += v2 + v3;
                *(__nv_bfloat162*)&outH[(size_t)m * ldc + n]     = __floats2bfloat162_rn(v0, v1);
                *(__nv_bfloat162*)&outH[(size_t)(m+8) * ldc + n] = __floats2bfloat162_rn(v2, v3);
                if (m == 0) { p0[n] = v0; p0[n+1] = v1; }   // exact row q=0
            } else if (EP == 0) {
                *(__nv_bfloat162*)&outH[(size_t)m * ldc + n]     = __floats2bfloat162_rn(v0, v1);
                *(__nv_bfloat162*)&outH[(size_t)(m+8) * ldc + n] = __floats2bfloat162_rn(v2, v3);
            } else if (EP == 2) {
                float b0v = bias[n], b1v = bias[n+1];
                v0 = fmaxf(v0 + b0v, 0.f); v1 = fmaxf(v1 + b1v, 0.f);
                v2 = fmaxf(v2 + b0v, 0.f); v3 = fmaxf(v3 + b1v, 0.f);
                __nv_bfloat162 h01 = __floats2bfloat162_rn(v0, v1);
                __nv_bfloat162 h23 = __floats2bfloat162_rn(v2, v3);
                float2 f01 = __bfloat1622float2(h01);
                float2 f23 = __bfloat1622float2(h23);
                __nv_bfloat162 l01 = __floats2bfloat162_rn(v0 - f01.x, v1 - f01.y);
                __nv_bfloat162 l23 = __floats2bfloat162_rn(v2 - f23.x, v3 - f23.y);
                *(__nv_bfloat162*)&outH[(size_t)m * ldc + n]            = h01;
                *(__nv_bfloat162*)&outH[(size_t)m * ldc + n + 1024]     = h01;
                *(__nv_bfloat162*)&outH[(size_t)m * ldc + n + 2048]     = l01;
                *(__nv_bfloat162*)&outH[(size_t)(m+8) * ldc + n]        = h23;
                *(__nv_bfloat162*)&outH[(size_t)(m+8) * ldc + n + 1024] = h23;
                *(__nv_bfloat162*)&outH[(size_t)(m+8) * ldc + n + 2048] = l23;
            } else {
                float b0v = bias[n], b1v = bias[n+1];
                *(float2*)&outF[(size_t)m * ldc + n]     = make_float2(v0 + b0v, v1 + b1v);
                *(float2*)&outF[(size_t)(m+8) * ldc + n] = make_float2(v2 + b0v, v3 + b1v);
            }
        }
        if (EP == 1) {
            rsum0 += __shfl_xor_sync(0xffffffffu, rsum0, 1);
            rsum0 += __shfl_xor_sync(0xffffffffu, rsum0, 2);
            rsum1 += __shfl_xor_sync(0xffffffffu, rsum1, 1);
            rsum1 += __shfl_xor_sync(0xffffffffu, rsum1, 2);
            if ((lane & 3) == 0) {
                atomicAdd(&rowsum[m0 + wm0 + mt*16 + er], rsum0);
                atomicAdd(&rowsum[m0 + wm0 + mt*16 + er + 8], rsum1);
            }
        }
    }
}

// ---------------- GEMM wrappers ----------------
__global__ void __launch_bounds__(256) k_proj() {
    int z = blockIdx.z; int h = z & 3; int sel = z >> 2;
    const bf16* A = sel ? g_memb : g_srcb;
    const bf16* W = (sel ? g_WQb : g_WKb) + (size_t)h * K_ * D_;
    bf16* C = (sel ? g_wqh : g_wkh) + (size_t)h * SB_ * K_;
    mma_core<0>(A, D_, W, D_, D_, blockIdx.y*128, blockIdx.x*128,
                nullptr, C, K_, nullptr, nullptr, nullptr);
}

__global__ void __launch_bounds__(256) k_gram() {
    int z = blockIdx.z; int h = z >> 2, b = z & 3;
    const bf16* A  = g_wqh + ((size_t)h * SB_ + b) * K_;
    const bf16* Bm = g_wkh + ((size_t)h * SB_ + b) * K_;
    bf16* C = g_P + (size_t)z * S_ * S_;
    mma_core<1>(A, B_*K_, Bm, B_*K_, K_, blockIdx.y*128, blockIdx.x*128,
                nullptr, C, S_, nullptr, g_rowsum + z * S_, g_P0 + z * S_);
}

__global__ void __launch_bounds__(256) k_ffn1(const float* __restrict__ l1b) {
    mma_core<2>(g_xs, 3*D_, g_l1ws, 3*D_, 3*D_, blockIdx.y*128, blockIdx.x*128,
                nullptr, g_h1s, 3*FF_, l1b, nullptr, nullptr);
}

__global__ void __launch_bounds__(256) k_ffn2(const float* __restrict__ l2b) {
    mma_core<3>(g_h1s, 3*FF_, g_l2ws, 3*FF_, 3*FF_, blockIdx.y*128, blockIdx.x*128,
                g_ff, nullptr, D_, l2b, nullptr, nullptr);
}

// ---------------- elementwise / reduction kernels ----------------
__global__ void k_cvt(const float* __restrict__ src, int which, int n) {
    bf16* dst;
    switch (which) {
        case 0: dst = g_srcb; break;
        case 1: dst = g_memb; break;
        case 2: dst = g_WKb;  break;
        default: dst = g_WQb; break;
    }
    int i = blockIdx.x * 256 + threadIdx.x;
    if (i * 4 < n) {
        float4 v = *(const float4*)(src + i*4);
        ((__nv_bfloat162*)dst)[i*2]   = __floats2bfloat162_rn(v.x, v.y);
        ((__nv_bfloat162*)dst)[i*2+1] = __floats2bfloat162_rn(v.z, v.w);
    }
}

__global__ void k_wsplit(const float* __restrict__ src, int which) {
    int len = which == 0 ? D_ : FF_;
    bf16* dst = which == 0 ? g_l1ws : g_l2ws;
    int i = blockIdx.x * 256 + threadIdx.x;
    int row = i / len, c = i % len;
    float v = src[i];
    bf16 hi = __float2bfloat16(v);
    bf16 lo = __float2bfloat16(v - __bfloat162float(hi));
    size_t base = (size_t)row * 3 * len;
    dst[base + c] = hi;
    dst[base + len + c] = lo;
    dst[base + 2*len + c] = hi;
}

__global__ void k_zero3() {
    int i = blockIdx.x * 256 + threadIdx.x;
    if (i < ZB_*S_) { g_rowsum[i] = 0.f; g_colsum[i] = 0.f; }
    if (i < ZB_*D_) g_ctx[i] = 0.f;
}

__global__ void k_l2norm() {
    __shared__ float red[4];
    size_t r = blockIdx.x;
    bf16* base = (r < (size_t)NH_*SB_) ? (g_wkh + r*K_) : (g_wqh + (r - (size_t)NH_*SB_)*K_);
    int t = threadIdx.x;
    uint4 u = *(uint4*)(base + 8*t);
    __nv_bfloat162* p = (__nv_bfloat162*)&u;
    float ss = 0.f;
    float vals[8];
#pragma unroll
    for (int i = 0; i < 4; i++) {
        float2 f = __bfloat1622float2(p[i]);
        vals[2*i] = f.x; vals[2*i+1] = f.y;
        ss += f.x*f.x + f.y*f.y;
    }
    ss = blk_sum(ss, red, 4);
    float sc = 1.f / fmaxf(sqrtf(ss), 1e-12f);
#pragma unroll
    for (int i = 0; i < 4; i++)
        p[i] = __floats2bfloat162_rn(vals[2*i]*sc, vals[2*i+1]*sc);
    *(uint4*)(base + 8*t) = u;
}

__global__ void k_inv() {
    int i = blockIdx.x * 256 + threadIdx.x;
    g_inv[i] = 1.f / g_rowsum[i];
}

// colsum over bf16 P: grid (S/256, ZB, S/128)
__global__ void k_colsum() {
    __shared__ float sinv[128];
    int z = blockIdx.y, qb = blockIdx.z;
    int t = threadIdx.x;
    if (t < 128) sinv[t] = g_inv[z*S_ + qb*128 + t];
    __syncthreads();
    int s = blockIdx.x * 256 + t;
    const bf16* P = g_P + (size_t)z*S_*S_ + (size_t)qb*128*S_ + s;
    float cs = 0.f;
#pragma unroll 4
    for (int q = 0; q < 128; q++)
        cs = fmaf(__bfloat162float(P[(size_t)q * S_]), sinv[q], cs);
    atomicAdd(&g_colsum[z*S_ + s], cs);
}

__global__ void k_aff0() {
    int i = blockIdx.x * 256 + threadIdx.x;   // z*S + s
    int z = i >> 11;
    float a0 = g_P0[i] * g_inv[z*S_];
    g_aff0[i] = a0 / (1e-9f + g_colsum[i]);
}

__global__ void k_ctx(const float* __restrict__ srcc) {
    int z = blockIdx.y; int b = z & 3;
    int d = threadIdx.x;
    int s0 = blockIdx.x * 256;
    float acc = 0.f;
    for (int si = 0; si < 256; si++) {
        int s = s0 + si;
        acc = fmaf(g_aff0[z*S_ + s], srcc[((size_t)s*B_ + b)*D_ + d], acc);
    }
    atomicAdd(&g_ctx[z*D_ + d], acc);
}

__global__ void k_head(const float* __restrict__ memory,
                       const float* __restrict__ WV, const float* __restrict__ Wt,
                       const float* __restrict__ e1w, const float* __restrict__ e1b,
                       const float* __restrict__ e2w, const float* __restrict__ e2b,
                       const float* __restrict__ eg,  const float* __restrict__ eb)
{
    __shared__ float cx[256], tv[256], rus[256], hm[1024], red[8];
    int z = blockIdx.x; int h = z >> 2, b = z & 3;
    int t = threadIdx.x;
    cx[t] = g_ctx[z*D_ + t];
    __syncthreads();

    const float* wv = WV + ((size_t)h*D_ + t) * D_;
    float o = 0.f;
#pragma unroll 4
    for (int d = 0; d < D_; d++) o = fmaf(wv[d], cx[d], o);
    tv[t] = memory[(size_t)b * D_ + t] - o;
    __syncthreads();

    const float* wt = Wt + ((size_t)h*D_ + t) * D_;
    float r = 0.f;
#pragma unroll 4
    for (int d = 0; d < D_; d++) r = fmaf(wt[d], tv[d], r);
    rus[t] = fmaxf(r, 0.f);
    __syncthreads();

#pragma unroll
    for (int i = 0; i < 4; i++) {
        int kx = i*256 + t;
        const float* w = e1w + ((size_t)h*K_ + kx) * D_;
        float v = e1b[h*K_ + kx];
#pragma unroll 4
        for (int d = 0; d < D_; d++) v = fmaf(w[d], rus[d], v);
        hm[kx] = fmaxf(v, 0.f);
    }
    __syncthreads();

    const float* w2 = e2w + ((size_t)h*D_ + t) * K_;
    float s2 = e2b[h*D_ + t];
#pragma unroll 4
    for (int kx = 0; kx < K_; kx++) s2 = fmaf(w2[kx], hm[kx], s2);

    float v = rus[t] + s2;
    g_xh[z*D_ + t] = ln256(v, eg[h*D_ + t], eb[h*D_ + t], red);
}

__global__ void k_out0(const float* __restrict__ Wout) {
    __shared__ float cat[1024];
    int b = blockIdx.x, d = threadIdx.x;
#pragma unroll
    for (int i = 0; i < 4; i++) cat[i*256 + d] = g_xh[(i*B_ + b)*D_ + d];
    __syncthreads();
    const float* w = Wout + (size_t)d * 1024;
    float acc = 0.f;
#pragma unroll 4
    for (int k = 0; k < 1024; k++) acc = fmaf(w[k], cat[k], acc);
    g_src2[b*D_ + d] = acc;
}

__global__ void k_ln1(const float* __restrict__ memory,
                      const float* __restrict__ n1g, const float* __restrict__ n1b) {
    __shared__ float red[8];
    int sb = blockIdx.x; int b = sb & 3; int t = threadIdx.x;
    float v = memory[(size_t)sb*D_ + t] + g_src2[b*D_ + t];
    float x = ln256(v, n1g[t], n1b[t], red);
    g_x[(size_t)sb*D_ + t] = x;
    bf16 hi = __float2bfloat16(x);
    bf16 lo = __float2bfloat16(x - __bfloat162float(hi));
    size_t base = (size_t)sb * 3 * D_;
    g_xs[base + t] = hi;
    g_xs[base + D_ + t] = hi;
    g_xs[base + 2*D_ + t] = lo;
}

__global__ void k_ln3(const float* __restrict__ n3g, const float* __restrict__ n3b,
                      float* __restrict__ out) {
    __shared__ float red[8];
    int sb = blockIdx.x; int t = threadIdx.x;
    float v = g_x[(size_t)sb*D_ + t] + g_ff[(size_t)sb*D_ + t];
    out[(size_t)sb*D_ + t] = ln256(v, n3g[t], n3b[t], red);
}

// ---------------- launch ----------------
extern "C" void kernel_launch(void* const* d_in, const int* in_sizes, int n_in,
                              void* d_out, int out_size) {
    (void)in_sizes; (void)n_in; (void)out_size;
    const float* srcc   = (const float*)d_in[0];
    const float* memory = (const float*)d_in[1];
    const float* WV   = (const float*)d_in[4];
    const float* Wt   = (const float*)d_in[5];
    const float* e1w  = (const float*)d_in[6];
    const float* e1b  = (const float*)d_in[7];
    const float* e2w  = (const float*)d_in[8];
    const float* e2b  = (const float*)d_in[9];
    const float* eg   = (const float*)d_in[10];
    const float* eb   = (const float*)d_in[11];
    const float* Wout = (const float*)d_in[12];
    const float* l1w  = (const float*)d_in[13];
    const float* l1b  = (const float*)d_in[14];
    const float* l2w  = (const float*)d_in[15];
    const float* l2b  = (const float*)d_in[16];
    const float* n1g  = (const float*)d_in[17];
    const float* n1b  = (const float*)d_in[18];
    const float* n3g  = (const float*)d_in[19];
    const float* n3b  = (const float*)d_in[20];
    float* out = (float*)d_out;

    k_zero3<<<(ZB_*S_ + 255)/256, 256>>>();
    k_cvt<<<SB_*D_/1024, 256>>>(srcc,   0, SB_*D_);
    k_cvt<<<SB_*D_/1024, 256>>>(memory, 1, SB_*D_);
    k_cvt<<<NH_*K_*D_/1024, 256>>>((const float*)d_in[2], 2, NH_*K_*D_);
    k_cvt<<<NH_*K_*D_/1024, 256>>>((const float*)d_in[3], 3, NH_*K_*D_);
    k_wsplit<<<FF_*D_/256, 256>>>(l1w, 0);
    k_wsplit<<<D_*FF_/256, 256>>>(l2w, 1);

    k_proj  <<<dim3(K_/128, SB_/128, 8), 256>>>();
    k_l2norm<<<2*NH_*SB_, 128>>>();
    k_gram  <<<dim3(S_/128, S_/128, ZB_), 256>>>();
    k_inv   <<<ZB_*S_/256, 256>>>();
    k_colsum<<<dim3(S_/256, ZB_, S_/128), 256>>>();
    k_aff0  <<<ZB_*S_/256, 256>>>();
    k_ctx   <<<dim3(S_/256, ZB_), 256>>>(srcc);
    k_head  <<<ZB_, 256>>>(memory, WV, Wt, e1w, e1b, e2w, e2b, eg, eb);
    k_out0  <<<B_, 256>>>(Wout);
    k_ln1   <<<SB_, 256>>>(memory, n1g, n1b);
    k_ffn1  <<<dim3(FF_/128, SB_/128), 256>>>(l1b);
    k_ffn2  <<<dim3(D_/128, SB_/128), 256>>>(l2b);
    k_ln3   <<<SB_, 256>>>(n3g, n3b, out);
}

// round 10
// speedup vs baseline: 1.1781x; 1.1781x over previous
#include <cuda_runtime.h>
#include <cuda_bf16.h>
#include <cstdint>

typedef __nv_bfloat16 bf16;

#define S_  2048
#define B_  4
#define D_  256
#define NH_ 4
#define K_  1024
#define FF_ 1024
#define SB_ (S_*B_)
#define ZB_ (NH_*B_)

// ---------------- scratch ----------------
static __device__ __align__(16) bf16  g_wqh[(size_t)NH_*SB_*K_];   // 64 MB
static __device__ __align__(16) bf16  g_wkh[(size_t)NH_*SB_*K_];   // 64 MB
static __device__ __align__(16) bf16  g_P  [(size_t)ZB_*S_*S_];    // 128 MB exp(dot) bf16
static __device__ float g_P0 [ZB_*S_];                             // exact row q=0
static __device__ float g_rowsum[ZB_*S_];
static __device__ float g_inv   [ZB_*S_];
static __device__ float g_colsum[ZB_*S_];
static __device__ float g_aff0  [ZB_*S_];
static __device__ float g_ctx[ZB_*D_];
static __device__ float g_xh [ZB_*D_];
static __device__ float g_src2[B_*D_];
static __device__ __align__(16) float g_x  [SB_*D_];
static __device__ __align__(16) float g_ff [SB_*D_];
// split-bf16 FFN operands:  A' = [hi|hi|lo],  B' = [hi|lo|hi]
static __device__ __align__(16) bf16 g_xs  [(size_t)SB_*3*D_];
static __device__ __align__(16) bf16 g_h1s [(size_t)SB_*3*FF_];
static __device__ __align__(16) bf16 g_l1ws[(size_t)FF_*3*D_];
static __device__ __align__(16) bf16 g_l2ws[(size_t)D_*3*FF_];
// bf16 copies of inputs (attention path)
static __device__ __align__(16) bf16 g_srcb[SB_*D_];
static __device__ __align__(16) bf16 g_memb[SB_*D_];
static __device__ __align__(16) bf16 g_WKb [NH_*K_*D_];
static __device__ __align__(16) bf16 g_WQb [NH_*K_*D_];

// ---------------- small helpers ----------------
__device__ __forceinline__ float blk_sum(float v, float* red, int nw) {
#pragma unroll
    for (int o = 16; o > 0; o >>= 1) v += __shfl_xor_sync(0xffffffffu, v, o);
    int w = threadIdx.x >> 5;
    if ((threadIdx.x & 31) == 0) red[w] = v;
    __syncthreads();
    float s = 0.f;
    for (int i = 0; i < nw; i++) s += red[i];
    __syncthreads();
    return s;
}
__device__ __forceinline__ float ln256(float v, float g, float b, float* red) {
    float mean = blk_sum(v, red, 8) * (1.f/256.f);
    float dv = v - mean;
    float var = blk_sum(dv*dv, red, 8) * (1.f/256.f);
    return dv * rsqrtf(var + 1e-5f) * g + b;
}
__device__ __forceinline__ unsigned sa(const void* p) {
    return (unsigned)__cvta_generic_to_shared(p);
}
// exp(x) for x in [-1.05, 1.05]: degree-9 Taylor, rel err < 3e-6, all FMA-pipe
__device__ __forceinline__ float expp(float x) {
    float r = 2.7557319e-6f;
    r = fmaf(r, x, 2.4801587e-5f);
    r = fmaf(r, x, 1.9841270e-4f);
    r = fmaf(r, x, 1.3888889e-3f);
    r = fmaf(r, x, 8.3333333e-3f);
    r = fmaf(r, x, 4.1666667e-2f);
    r = fmaf(r, x, 1.6666667e-1f);
    r = fmaf(r, x, 0.5f);
    r = fmaf(r, x, 1.0f);
    r = fmaf(r, x, 1.0f);
    return r;
}

// ---------------- bf16 HMMA GEMM core (R5 structure) ----------------
// C[M,N] = epi(A[M,Kd] @ B[N,Kd]^T), bf16 K-contiguous, fp32 accum.
// Block 128x128, BK=32, 256 threads = 8 warps (warp tile 64x32, 2x4 grid).
// EP: 0 bf16 raw, 1 exp(poly)->bf16 P + f32 row0 + rowsum atomics,
//     2 relu+bias -> split triple bf16, 3 bias -> f32
template<int EP>
__device__ __forceinline__ void mma_core(
    const bf16* __restrict__ A, int lda,
    const bf16* __restrict__ Bw, int ldb,
    int Kd, int m0, int n0,
    float* __restrict__ outF, bf16* __restrict__ outH, int ldc,
    const float* __restrict__ bias, float* __restrict__ rowsum, float* __restrict__ p0)
{
    __shared__ __align__(16) bf16 As[2][128][40];
    __shared__ __align__(16) bf16 Bs[2][128][40];

    const int tid  = threadIdx.x;
    const int lane = tid & 31;
    const int wid  = tid >> 5;
    const int wm0  = (wid & 1) * 64;
    const int wn0  = (wid >> 1) * 32;

    const int c0 = tid, c1 = tid + 256;
    const int ar0 = c0 >> 2, ak0 = (c0 & 3) * 8;
    const int ar1 = c1 >> 2, ak1 = (c1 & 3) * 8;

    float acc[4][4][4];
#pragma unroll
    for (int i = 0; i < 4; i++)
#pragma unroll
        for (int j = 0; j < 4; j++)
#pragma unroll
            for (int k = 0; k < 4; k++) acc[i][j][k] = 0.f;

    const int nK = Kd >> 5;

    {
        const bf16* a0 = A  + (size_t)(m0 + ar0) * lda + ak0;
        const bf16* a1 = A  + (size_t)(m0 + ar1) * lda + ak1;
        const bf16* b0 = Bw + (size_t)(n0 + ar0) * ldb + ak0;
        const bf16* b1 = Bw + (size_t)(n0 + ar1) * ldb + ak1;
        asm volatile("cp.async.cg.shared.global [%0],[%1],16;\n"::"r"(sa(&As[0][ar0][ak0])),"l"(a0));
        asm volatile("cp.async.cg.shared.global [%0],[%1],16;\n"::"r"(sa(&As[0][ar1][ak1])),"l"(a1));
        asm volatile("cp.async.cg.shared.global [%0],[%1],16;\n"::"r"(sa(&Bs[0][ar0][ak0])),"l"(b0));
        asm volatile("cp.async.cg.shared.global [%0],[%1],16;\n"::"r"(sa(&Bs[0][ar1][ak1])),"l"(b1));
        asm volatile("cp.async.commit_group;\n");
    }

    for (int kb = 0; kb < nK; kb++) {
        asm volatile("cp.async.wait_group 0;\n");
        __syncthreads();
        if (kb + 1 < nK) {
            int st = (kb + 1) & 1;
            int ko = (kb + 1) * 32;
            const bf16* a0 = A  + (size_t)(m0 + ar0) * lda + ko + ak0;
            const bf16* a1 = A  + (size_t)(m0 + ar1) * lda + ko + ak1;
            const bf16* b0 = Bw + (size_t)(n0 + ar0) * ldb + ko + ak0;
            const bf16* b1 = Bw + (size_t)(n0 + ar1) * ldb + ko + ak1;
            asm volatile("cp.async.cg.shared.global [%0],[%1],16;\n"::"r"(sa(&As[st][ar0][ak0])),"l"(a0));
            asm volatile("cp.async.cg.shared.global [%0],[%1],16;\n"::"r"(sa(&As[st][ar1][ak1])),"l"(a1));
            asm volatile("cp.async.cg.shared.global [%0],[%1],16;\n"::"r"(sa(&Bs[st][ar0][ak0])),"l"(b0));
            asm volatile("cp.async.cg.shared.global [%0],[%1],16;\n"::"r"(sa(&Bs[st][ar1][ak1])),"l"(b1));
            asm volatile("cp.async.commit_group;\n");
        }
        int st = kb & 1;
#pragma unroll
        for (int ks = 0; ks < 2; ks++) {
            unsigned a[4][4];
            unsigned bfr[4][2];
#pragma unroll
            for (int mt = 0; mt < 4; mt++) {
                unsigned ad = sa(&As[st][wm0 + mt*16 + (lane & 15)][ks*16 + (lane >> 4)*8]);
                asm volatile("ldmatrix.sync.aligned.m8n8.x4.shared.b16 {%0,%1,%2,%3},[%4];\n"
                    : "=r"(a[mt][0]), "=r"(a[mt][1]), "=r"(a[mt][2]), "=r"(a[mt][3]) : "r"(ad));
            }
#pragma unroll
            for (int bp = 0; bp < 2; bp++) {
                unsigned r0, r1, r2, r3;
                unsigned ad = sa(&Bs[st][wn0 + bp*16 + (lane & 15)][ks*16 + (lane >> 4)*8]);
                asm volatile("ldmatrix.sync.aligned.m8n8.x4.shared.b16 {%0,%1,%2,%3},[%4];\n"
                    : "=r"(r0), "=r"(r1), "=r"(r2), "=r"(r3) : "r"(ad));
                bfr[bp*2  ][0] = r0; bfr[bp*2  ][1] = r2;
                bfr[bp*2+1][0] = r1; bfr[bp*2+1][1] = r3;
            }
#pragma unroll
            for (int mt = 0; mt < 4; mt++)
#pragma unroll
                for (int nt = 0; nt < 4; nt++) {
                    asm volatile(
                        "mma.sync.aligned.m16n8k16.row.col.f32.bf16.bf16.f32 "
                        "{%0,%1,%2,%3},{%4,%5,%6,%7},{%8,%9},{%0,%1,%2,%3};\n"
                        : "+f"(acc[mt][nt][0]), "+f"(acc[mt][nt][1]),
                          "+f"(acc[mt][nt][2]), "+f"(acc[mt][nt][3])
                        : "r"(a[mt][0]), "r"(a[mt][1]), "r"(a[mt][2]), "r"(a[mt][3]),
                          "r"(bfr[nt][0]), "r"(bfr[nt][1]));
                }
        }
        __syncthreads();
    }

    // ---------------- epilogue ----------------
    const int er = lane >> 2;
    const int ec = (lane & 3) * 2;
#pragma unroll
    for (int mt = 0; mt < 4; mt++) {
        float rsum0 = 0.f, rsum1 = 0.f;
#pragma unroll
        for (int nt = 0; nt < 4; nt++) {
            int m = m0 + wm0 + mt*16 + er;
            int n = n0 + wn0 + nt*8 + ec;
            float v0 = acc[mt][nt][0], v1 = acc[mt][nt][1];
            float v2 = acc[mt][nt][2], v3 = acc[mt][nt][3];
            if (EP == 1) {
                v0 = expp(v0); v1 = expp(v1); v2 = expp(v2); v3 = expp(v3);
                rsum0 += v0 + v1; rsum1 += v2 + v3;
                *(__nv_bfloat162*)&outH[(size_t)m * ldc + n]     = __floats2bfloat162_rn(v0, v1);
                *(__nv_bfloat162*)&outH[(size_t)(m+8) * ldc + n] = __floats2bfloat162_rn(v2, v3);
                if (m == 0) { p0[n] = v0; p0[n+1] = v1; }   // exact row q=0
            } else if (EP == 0) {
                *(__nv_bfloat162*)&outH[(size_t)m * ldc + n]     = __floats2bfloat162_rn(v0, v1);
                *(__nv_bfloat162*)&outH[(size_t)(m+8) * ldc + n] = __floats2bfloat162_rn(v2, v3);
            } else if (EP == 2) {
                float b0v = bias[n], b1v = bias[n+1];
                v0 = fmaxf(v0 + b0v, 0.f); v1 = fmaxf(v1 + b1v, 0.f);
                v2 = fmaxf(v2 + b0v, 0.f); v3 = fmaxf(v3 + b1v, 0.f);
                __nv_bfloat162 h01 = __floats2bfloat162_rn(v0, v1);
                __nv_bfloat162 h23 = __floats2bfloat162_rn(v2, v3);
                float2 f01 = __bfloat1622float2(h01);
                float2 f23 = __bfloat1622float2(h23);
                __nv_bfloat162 l01 = __floats2bfloat162_rn(v0 - f01.x, v1 - f01.y);
                __nv_bfloat162 l23 = __floats2bfloat162_rn(v2 - f23.x, v3 - f23.y);
                *(__nv_bfloat162*)&outH[(size_t)m * ldc + n]            = h01;
                *(__nv_bfloat162*)&outH[(size_t)m * ldc + n + 1024]     = h01;
                *(__nv_bfloat162*)&outH[(size_t)m * ldc + n + 2048]     = l01;
                *(__nv_bfloat162*)&outH[(size_t)(m+8) * ldc + n]        = h23;
                *(__nv_bfloat162*)&outH[(size_t)(m+8) * ldc + n + 1024] = h23;
                *(__nv_bfloat162*)&outH[(size_t)(m+8) * ldc + n + 2048] = l23;
            } else {
                float b0v = bias[n], b1v = bias[n+1];
                *(float2*)&outF[(size_t)m * ldc + n]     = make_float2(v0 + b0v, v1 + b1v);
                *(float2*)&outF[(size_t)(m+8) * ldc + n] = make_float2(v2 + b0v, v3 + b1v);
            }
        }
        if (EP == 1) {
            rsum0 += __shfl_xor_sync(0xffffffffu, rsum0, 1);
            rsum0 += __shfl_xor_sync(0xffffffffu, rsum0, 2);
            rsum1 += __shfl_xor_sync(0xffffffffu, rsum1, 1);
            rsum1 += __shfl_xor_sync(0xffffffffu, rsum1, 2);
            if ((lane & 3) == 0) {
                atomicAdd(&rowsum[m0 + wm0 + mt*16 + er], rsum0);
                atomicAdd(&rowsum[m0 + wm0 + mt*16 + er + 8], rsum1);
            }
        }
    }
}

// ---------------- GEMM wrappers ----------------
__global__ void __launch_bounds__(256) k_proj() {
    int z = blockIdx.z; int h = z & 3; int sel = z >> 2;
    const bf16* A = sel ? g_memb : g_srcb;
    const bf16* W = (sel ? g_WQb : g_WKb) + (size_t)h * K_ * D_;
    bf16* C = (sel ? g_wqh : g_wkh) + (size_t)h * SB_ * K_;
    mma_core<0>(A, D_, W, D_, D_, blockIdx.y*128, blockIdx.x*128,
                nullptr, C, K_, nullptr, nullptr, nullptr);
}

__global__ void __launch_bounds__(256) k_gram() {
    int z = blockIdx.z; int h = z >> 2, b = z & 3;
    const bf16* A  = g_wqh + ((size_t)h * SB_ + b) * K_;
    const bf16* Bm = g_wkh + ((size_t)h * SB_ + b) * K_;
    bf16* C = g_P + (size_t)z * S_ * S_;
    mma_core<1>(A, B_*K_, Bm, B_*K_, K_, blockIdx.y*128, blockIdx.x*128,
                nullptr, C, S_, nullptr, g_rowsum + z * S_, g_P0 + z * S_);
}

__global__ void __launch_bounds__(256) k_ffn1(const float* __restrict__ l1b) {
    mma_core<2>(g_xs, 3*D_, g_l1ws, 3*D_, 3*D_, blockIdx.y*128, blockIdx.x*128,
                nullptr, g_h1s, 3*FF_, l1b, nullptr, nullptr);
}

__global__ void __launch_bounds__(256) k_ffn2(const float* __restrict__ l2b) {
    mma_core<3>(g_h1s, 3*FF_, g_l2ws, 3*FF_, 3*FF_, blockIdx.y*128, blockIdx.x*128,
                g_ff, nullptr, D_, l2b, nullptr, nullptr);
}

// ---------------- elementwise / reduction kernels ----------------
__global__ void k_cvt(const float* __restrict__ src, int which, int n) {
    bf16* dst;
    switch (which) {
        case 0: dst = g_srcb; break;
        case 1: dst = g_memb; break;
        case 2: dst = g_WKb;  break;
        default: dst = g_WQb; break;
    }
    int i = blockIdx.x * 256 + threadIdx.x;
    if (i * 4 < n) {
        float4 v = *(const float4*)(src + i*4);
        ((__nv_bfloat162*)dst)[i*2]   = __floats2bfloat162_rn(v.x, v.y);
        ((__nv_bfloat162*)dst)[i*2+1] = __floats2bfloat162_rn(v.z, v.w);
    }
}

__global__ void k_wsplit(const float* __restrict__ src, int which) {
    int len = which == 0 ? D_ : FF_;
    bf16* dst = which == 0 ? g_l1ws : g_l2ws;
    int i = blockIdx.x * 256 + threadIdx.x;
    int row = i / len, c = i % len;
    float v = src[i];
    bf16 hi = __float2bfloat16(v);
    bf16 lo = __float2bfloat16(v - __bfloat162float(hi));
    size_t base = (size_t)row * 3 * len;
    dst[base + c] = hi;
    dst[base + len + c] = lo;
    dst[base + 2*len + c] = hi;
}

__global__ void k_zero3() {
    int i = blockIdx.x * 256 + threadIdx.x;
    if (i < ZB_*S_) { g_rowsum[i] = 0.f; g_colsum[i] = 0.f; }
    if (i < ZB_*D_) g_ctx[i] = 0.f;
}

__global__ void k_l2norm() {
    __shared__ float red[4];
    size_t r = blockIdx.x;
    bf16* base = (r < (size_t)NH_*SB_) ? (g_wkh + r*K_) : (g_wqh + (r - (size_t)NH_*SB_)*K_);
    int t = threadIdx.x;
    uint4 u = *(uint4*)(base + 8*t);
    __nv_bfloat162* p = (__nv_bfloat162*)&u;
    float ss = 0.f;
    float vals[8];
#pragma unroll
    for (int i = 0; i < 4; i++) {
        float2 f = __bfloat1622float2(p[i]);
        vals[2*i] = f.x; vals[2*i+1] = f.y;
        ss += f.x*f.x + f.y*f.y;
    }
    ss = blk_sum(ss, red, 4);
    float sc = 1.f / fmaxf(sqrtf(ss), 1e-12f);
#pragma unroll
    for (int i = 0; i < 4; i++)
        p[i] = __floats2bfloat162_rn(vals[2*i]*sc, vals[2*i+1]*sc);
    *(uint4*)(base + 8*t) = u;
}

__global__ void k_inv() {
    int i = blockIdx.x * 256 + threadIdx.x;
    g_inv[i] = 1.f / g_rowsum[i];
}

// colsum over bf16 P: grid (S/256, ZB, S/128)
__global__ void k_colsum() {
    __shared__ float sinv[128];
    int z = blockIdx.y, qb = blockIdx.z;
    int t = threadIdx.x;
    if (t < 128) sinv[t] = g_inv[z*S_ + qb*128 + t];
    __syncthreads();
    int s = blockIdx.x * 256 + t;
    const bf16* P = g_P + (size_t)z*S_*S_ + (size_t)qb*128*S_ + s;
    float cs = 0.f;
#pragma unroll 4
    for (int q = 0; q < 128; q++)
        cs = fmaf(__bfloat162float(P[(size_t)q * S_]), sinv[q], cs);
    atomicAdd(&g_colsum[z*S_ + s], cs);
}

__global__ void k_aff0() {
    int i = blockIdx.x * 256 + threadIdx.x;   // z*S + s
    int z = i >> 11;
    float a0 = g_P0[i] * g_inv[z*S_];
    g_aff0[i] = a0 / (1e-9f + g_colsum[i]);
}

__global__ void k_ctx(const float* __restrict__ srcc) {
    int z = blockIdx.y; int b = z & 3;
    int d = threadIdx.x;
    int s0 = blockIdx.x * 256;
    float acc = 0.f;
    for (int si = 0; si < 256; si++) {
        int s = s0 + si;
        acc = fmaf(g_aff0[z*S_ + s], srcc[((size_t)s*B_ + b)*D_ + d], acc);
    }
    atomicAdd(&g_ctx[z*D_ + d], acc);
}

__global__ void k_head(const float* __restrict__ memory,
                       const float* __restrict__ WV, const float* __restrict__ Wt,
                       const float* __restrict__ e1w, const float* __restrict__ e1b,
                       const float* __restrict__ e2w, const float* __restrict__ e2b,
                       const float* __restrict__ eg,  const float* __restrict__ eb)
{
    __shared__ float cx[256], tv[256], rus[256], hm[1024], red[8];
    int z = blockIdx.x; int h = z >> 2, b = z & 3;
    int t = threadIdx.x;
    cx[t] = g_ctx[z*D_ + t];
    __syncthreads();

    const float* wv = WV + ((size_t)h*D_ + t) * D_;
    float o = 0.f;
#pragma unroll 4
    for (int d = 0; d < D_; d++) o = fmaf(wv[d], cx[d], o);
    tv[t] = memory[(size_t)b * D_ + t] - o;
    __syncthreads();

    const float* wt = Wt + ((size_t)h*D_ + t) * D_;
    float r = 0.f;
#pragma unroll 4
    for (int d = 0; d < D_; d++) r = fmaf(wt[d], tv[d], r);
    rus[t] = fmaxf(r, 0.f);
    __syncthreads();

#pragma unroll
    for (int i = 0; i < 4; i++) {
        int kx = i*256 + t;
        const float* w = e1w + ((size_t)h*K_ + kx) * D_;
        float v = e1b[h*K_ + kx];
#pragma unroll 4
        for (int d = 0; d < D_; d++) v = fmaf(w[d], rus[d], v);
        hm[kx] = fmaxf(v, 0.f);
    }
    __syncthreads();

    const float* w2 = e2w + ((size_t)h*D_ + t) * K_;
    float s2 = e2b[h*D_ + t];
#pragma unroll 4
    for (int kx = 0; kx < K_; kx++) s2 = fmaf(w2[kx], hm[kx], s2);

    float v = rus[t] + s2;
    g_xh[z*D_ + t] = ln256(v, eg[h*D_ + t], eb[h*D_ + t], red);
}

__global__ void k_out0(const float* __restrict__ Wout) {
    __shared__ float cat[1024];
    int b = blockIdx.x, d = threadIdx.x;
#pragma unroll
    for (int i = 0; i < 4; i++) cat[i*256 + d] = g_xh[(i*B_ + b)*D_ + d];
    __syncthreads();
    const float* w = Wout + (size_t)d * 1024;
    float acc = 0.f;
#pragma unroll 4
    for (int k = 0; k < 1024; k++) acc = fmaf(w[k], cat[k], acc);
    g_src2[b*D_ + d] = acc;
}

__global__ void k_ln1(const float* __restrict__ memory,
                      const float* __restrict__ n1g, const float* __restrict__ n1b) {
    __shared__ float red[8];
    int sb = blockIdx.x; int b = sb & 3; int t = threadIdx.x;
    float v = memory[(size_t)sb*D_ + t] + g_src2[b*D_ + t];
    float x = ln256(v, n1g[t], n1b[t], red);
    g_x[(size_t)sb*D_ + t] = x;
    bf16 hi = __float2bfloat16(x);
    bf16 lo = __float2bfloat16(x - __bfloat162float(hi));
    size_t base = (size_t)sb * 3 * D_;
    g_xs[base + t] = hi;
    g_xs[base + D_ + t] = hi;
    g_xs[base + 2*D_ + t] = lo;
}

__global__ void k_ln3(const float* __restrict__ n3g, const float* __restrict__ n3b,
                      float* __restrict__ out) {
    __shared__ float red[8];
    int sb = blockIdx.x; int t = threadIdx.x;
    float v = g_x[(size_t)sb*D_ + t] + g_ff[(size_t)sb*D_ + t];
    out[(size_t)sb*D_ + t] = ln256(v, n3g[t], n3b[t], red);
}

// ---------------- launch ----------------
extern "C" void kernel_launch(void* const* d_in, const int* in_sizes, int n_in,
                              void* d_out, int out_size) {
    (void)in_sizes; (void)n_in; (void)out_size;
    const float* srcc   = (const float*)d_in[0];
    const float* memory = (const float*)d_in[1];
    const float* WV   = (const float*)d_in[4];
    const float* Wt   = (const float*)d_in[5];
    const float* e1w  = (const float*)d_in[6];
    const float* e1b  = (const float*)d_in[7];
    const float* e2w  = (const float*)d_in[8];
    const float* e2b  = (const float*)d_in[9];
    const float* eg   = (const float*)d_in[10];
    const float* eb   = (const float*)d_in[11];
    const float* Wout = (const float*)d_in[12];
    const float* l1w  = (const float*)d_in[13];
    const float* l1b  = (const float*)d_in[14];
    const float* l2w  = (const float*)d_in[15];
    const float* l2b  = (const float*)d_in[16];
    const float* n1g  = (const float*)d_in[17];
    const float* n1b  = (const float*)d_in[18];
    const float* n3g  = (const float*)d_in[19];
    const float* n3b  = (const float*)d_in[20];
    float* out = (float*)d_out;

    k_zero3<<<(ZB_*S_ + 255)/256, 256>>>();
    k_cvt<<<SB_*D_/1024, 256>>>(srcc,   0, SB_*D_);
    k_cvt<<<SB_*D_/1024, 256>>>(memory, 1, SB_*D_);
    k_cvt<<<NH_*K_*D_/1024, 256>>>((const float*)d_in[2], 2, NH_*K_*D_);
    k_cvt<<<NH_*K_*D_/1024, 256>>>((const float*)d_in[3], 3, NH_*K_*D_);
    k_wsplit<<<FF_*D_/256, 256>>>(l1w, 0);
    k_wsplit<<<D_*FF_/256, 256>>>(l2w, 1);

    k_proj  <<<dim3(K_/128, SB_/128, 8), 256>>>();
    k_l2norm<<<2*NH_*SB_, 128>>>();
    k_gram  <<<dim3(S_/128, S_/128, ZB_), 256>>>();
    k_inv   <<<ZB_*S_/256, 256>>>();
    k_colsum<<<dim3(S_/256, ZB_, S_/128), 256>>>();
    k_aff0  <<<ZB_*S_/256, 256>>>();
    k_ctx   <<<dim3(S_/256, ZB_), 256>>>(srcc);
    k_head  <<<ZB_, 256>>>(memory, WV, Wt, e1w, e1b, e2w, e2b, eg, eb);
    k_out0  <<<B_, 256>>>(Wout);
    k_ln1   <<<SB_, 256>>>(memory, n1g, n1b);
    k_ffn1  <<<dim3(FF_/128, SB_/128), 256>>>(l1b);
    k_ffn2  <<<dim3(D_/128, SB_/128), 256>>>(l2b);
    k_ln3   <<<SB_, 256>>>(n3g, n3b, out);
}

// round 12
// speedup vs baseline: 1.2005x; 1.0190x over previous
#include <cuda_runtime.h>
#include <cuda_bf16.h>
#include <cstdint>

typedef __nv_bfloat16 bf16;

#define S_  2048
#define B_  4
#define D_  256
#define NH_ 4
#define K_  1024
#define FF_ 1024
#define SB_ (S_*B_)
#define ZB_ (NH_*B_)

// ---------------- scratch ----------------
// wq/wk stored UNNORMALIZED in [h][b][s][k] layout (lda = K_)
static __device__ __align__(16) bf16  g_wqh[(size_t)NH_*SB_*K_];   // 64 MB
static __device__ __align__(16) bf16  g_wkh[(size_t)NH_*SB_*K_];   // 64 MB
static __device__ __align__(16) bf16  g_P  [(size_t)ZB_*S_*S_];    // 128 MB exp(dot) bf16
static __device__ float g_P0 [ZB_*S_];                             // exact row q=0
static __device__ float g_ssq[NH_*SB_];   // sum-of-squares -> inv norm (wq), [h][b*S+s]
static __device__ float g_ssk[NH_*SB_];   // same for wk
static __device__ float g_rowsum[ZB_*S_];
static __device__ float g_colsum[ZB_*S_];
static __device__ float g_aff0  [ZB_*S_];
static __device__ float g_ctx[ZB_*D_];
static __device__ float g_xh [ZB_*D_];
static __device__ float g_src2[B_*D_];
static __device__ __align__(16) float g_x  [SB_*D_];
static __device__ __align__(16) float g_ff [SB_*D_];
// split-bf16 FFN operands:  A' = [hi|hi|lo],  B' = [hi|lo|hi]
static __device__ __align__(16) bf16 g_xs  [(size_t)SB_*3*D_];
static __device__ __align__(16) bf16 g_h1s [(size_t)SB_*3*FF_];
static __device__ __align__(16) bf16 g_l1ws[(size_t)FF_*3*D_];
static __device__ __align__(16) bf16 g_l2ws[(size_t)D_*3*FF_];
// bf16 copies of inputs (attention path)
static __device__ __align__(16) bf16 g_srcb[SB_*D_];
static __device__ __align__(16) bf16 g_memb[SB_*D_];
static __device__ __align__(16) bf16 g_WKb [NH_*K_*D_];
static __device__ __align__(16) bf16 g_WQb [NH_*K_*D_];

// ---------------- small helpers ----------------
__device__ __forceinline__ float blk_sum(float v, float* red, int nw) {
#pragma unroll
    for (int o = 16; o > 0; o >>= 1) v += __shfl_xor_sync(0xffffffffu, v, o);
    int w = threadIdx.x >> 5;
    if ((threadIdx.x & 31) == 0) red[w] = v;
    __syncthreads();
    float s = 0.f;
    for (int i = 0; i < nw; i++) s += red[i];
    __syncthreads();
    return s;
}
__device__ __forceinline__ float ln256(float v, float g, float b, float* red) {
    float mean = blk_sum(v, red, 8) * (1.f/256.f);
    float dv = v - mean;
    float var = blk_sum(dv*dv, red, 8) * (1.f/256.f);
    return dv * rsqrtf(var + 1e-5f) * g + b;
}
__device__ __forceinline__ unsigned sa(const void* p) {
    return (unsigned)__cvta_generic_to_shared(p);
}
// exp(x) for x in [-1.05, 1.05]: degree-9 Taylor, rel err < 3e-6, all FMA-pipe
__device__ __forceinline__ float expp(float x) {
    float r = 2.7557319e-6f;
    r = fmaf(r, x, 2.4801587e-5f);
    r = fmaf(r, x, 1.9841270e-4f);
    r = fmaf(r, x, 1.3888889e-3f);
    r = fmaf(r, x, 8.3333333e-3f);
    r = fmaf(r, x, 4.1666667e-2f);
    r = fmaf(r, x, 1.6666667e-1f);
    r = fmaf(r, x, 0.5f);
    r = fmaf(r, x, 1.0f);
    r = fmaf(r, x, 1.0f);
    return r;
}

// ---------------- bf16 HMMA GEMM core (R5 structure) ----------------
// C[M,N] = epi(A[M,Kd] @ B[N,Kd]^T), bf16 K-contiguous, fp32 accum.
// Block 128x128, BK=32, 256 threads = 8 warps (warp tile 64x32, 2x4 grid).
// EP: 1 scale(invq,invk)+exp(poly)->bf16 P + f32 row0 + rowsum atomics,
//     2 relu+bias -> split triple bf16, 3 bias -> f32,
//     4 proj: bf16 raw to PERMUTED rows ((m&3)*S+(m>>2)) + sum-of-squares atomics
template<int EP>
__device__ __forceinline__ void mma_core(
    const bf16* __restrict__ A, int lda,
    const bf16* __restrict__ Bw, int ldb,
    int Kd, int m0, int n0,
    float* __restrict__ outF, bf16* __restrict__ outH, int ldc,
    const float* __restrict__ bias, float* __restrict__ rowsum, float* __restrict__ p0,
    const float* __restrict__ invq, const float* __restrict__ invk)
{
    __shared__ __align__(16) bf16 As[2][128][40];
    __shared__ __align__(16) bf16 Bs[2][128][40];

    const int tid  = threadIdx.x;
    const int lane = tid & 31;
    const int wid  = tid >> 5;
    const int wm0  = (wid & 1) * 64;
    const int wn0  = (wid >> 1) * 32;

    const int c0 = tid, c1 = tid + 256;
    const int ar0 = c0 >> 2, ak0 = (c0 & 3) * 8;
    const int ar1 = c1 >> 2, ak1 = (c1 & 3) * 8;

    float acc[4][4][4];
#pragma unroll
    for (int i = 0; i < 4; i++)
#pragma unroll
        for (int j = 0; j < 4; j++)
#pragma unroll
            for (int k = 0; k < 4; k++) acc[i][j][k] = 0.f;

    const int nK = Kd >> 5;

    {
        const bf16* a0 = A  + (size_t)(m0 + ar0) * lda + ak0;
        const bf16* a1 = A  + (size_t)(m0 + ar1) * lda + ak1;
        const bf16* b0 = Bw + (size_t)(n0 + ar0) * ldb + ak0;
        const bf16* b1 = Bw + (size_t)(n0 + ar1) * ldb + ak1;
        asm volatile("cp.async.cg.shared.global [%0],[%1],16;\n"::"r"(sa(&As[0][ar0][ak0])),"l"(a0));
        asm volatile("cp.async.cg.shared.global [%0],[%1],16;\n"::"r"(sa(&As[0][ar1][ak1])),"l"(a1));
        asm volatile("cp.async.cg.shared.global [%0],[%1],16;\n"::"r"(sa(&Bs[0][ar0][ak0])),"l"(b0));
        asm volatile("cp.async.cg.shared.global [%0],[%1],16;\n"::"r"(sa(&Bs[0][ar1][ak1])),"l"(b1));
        asm volatile("cp.async.commit_group;\n");
    }

    for (int kb = 0; kb < nK; kb++) {
        asm volatile("cp.async.wait_group 0;\n");
        __syncthreads();
        if (kb + 1 < nK) {
            int st = (kb + 1) & 1;
            int ko = (kb + 1) * 32;
            const bf16* a0 = A  + (size_t)(m0 + ar0) * lda + ko + ak0;
            const bf16* a1 = A  + (size_t)(m0 + ar1) * lda + ko + ak1;
            const bf16* b0 = Bw + (size_t)(n0 + ar0) * ldb + ko + ak0;
            const bf16* b1 = Bw + (size_t)(n0 + ar1) * ldb + ko + ak1;
            asm volatile("cp.async.cg.shared.global [%0],[%1],16;\n"::"r"(sa(&As[st][ar0][ak0])),"l"(a0));
            asm volatile("cp.async.cg.shared.global [%0],[%1],16;\n"::"r"(sa(&As[st][ar1][ak1])),"l"(a1));
            asm volatile("cp.async.cg.shared.global [%0],[%1],16;\n"::"r"(sa(&Bs[st][ar0][ak0])),"l"(b0));
            asm volatile("cp.async.cg.shared.global [%0],[%1],16;\n"::"r"(sa(&Bs[st][ar1][ak1])),"l"(b1));
            asm volatile("cp.async.commit_group;\n");
        }
        int st = kb & 1;
#pragma unroll
        for (int ks = 0; ks < 2; ks++) {
            unsigned a[4][4];
            unsigned bfr[4][2];
#pragma unroll
            for (int mt = 0; mt < 4; mt++) {
                unsigned ad = sa(&As[st][wm0 + mt*16 + (lane & 15)][ks*16 + (lane >> 4)*8]);
                asm volatile("ldmatrix.sync.aligned.m8n8.x4.shared.b16 {%0,%1,%2,%3},[%4];\n"
                    : "=r"(a[mt][0]), "=r"(a[mt][1]), "=r"(a[mt][2]), "=r"(a[mt][3]) : "r"(ad));
            }
#pragma unroll
            for (int bp = 0; bp < 2; bp++) {
                unsigned r0, r1, r2, r3;
                unsigned ad = sa(&Bs[st][wn0 + bp*16 + (lane & 15)][ks*16 + (lane >> 4)*8]);
                asm volatile("ldmatrix.sync.aligned.m8n8.x4.shared.b16 {%0,%1,%2,%3},[%4];\n"
                    : "=r"(r0), "=r"(r1), "=r"(r2), "=r"(r3) : "r"(ad));
                bfr[bp*2  ][0] = r0; bfr[bp*2  ][1] = r2;
                bfr[bp*2+1][0] = r1; bfr[bp*2+1][1] = r3;
            }
#pragma unroll
            for (int mt = 0; mt < 4; mt++)
#pragma unroll
                for (int nt = 0; nt < 4; nt++) {
                    asm volatile(
                        "mma.sync.aligned.m16n8k16.row.col.f32.bf16.bf16.f32 "
                        "{%0,%1,%2,%3},{%4,%5,%6,%7},{%8,%9},{%0,%1,%2,%3};\n"
                        : "+f"(acc[mt][nt][0]), "+f"(acc[mt][nt][1]),
                          "+f"(acc[mt][nt][2]), "+f"(acc[mt][nt][3])
                        : "r"(a[mt][0]), "r"(a[mt][1]), "r"(a[mt][2]), "r"(a[mt][3]),
                          "r"(bfr[nt][0]), "r"(bfr[nt][1]));
                }
        }
        __syncthreads();
    }

    // ---------------- epilogue ----------------
    const int er = lane >> 2;
    const int ec = (lane & 3) * 2;
#pragma unroll
    for (int mt = 0; mt < 4; mt++) {
        float rsum0 = 0.f, rsum1 = 0.f;
        const int m = m0 + wm0 + mt*16 + er;
        float iq0 = 0.f, iq1 = 0.f;
        if (EP == 1) { iq0 = invq[m]; iq1 = invq[m + 8]; }
#pragma unroll
        for (int nt = 0; nt < 4; nt++) {
            int n = n0 + wn0 + nt*8 + ec;
            float v0 = acc[mt][nt][0], v1 = acc[mt][nt][1];
            float v2 = acc[mt][nt][2], v3 = acc[mt][nt][3];
            if (EP == 1) {
                float ik0 = invk[n], ik1 = invk[n+1];
                v0 = expp(v0 * iq0 * ik0); v1 = expp(v1 * iq0 * ik1);
                v2 = expp(v2 * iq1 * ik0); v3 = expp(v3 * iq1 * ik1);
                rsum0 += v0 + v1; rsum1 += v2 + v3;
                *(__nv_bfloat162*)&outH[(size_t)m * ldc + n]     = __floats2bfloat162_rn(v0, v1);
                *(__nv_bfloat162*)&outH[(size_t)(m+8) * ldc + n] = __floats2bfloat162_rn(v2, v3);
                if (m == 0) { p0[n] = v0; p0[n+1] = v1; }   // exact row q=0
            } else if (EP == 4) {
                int pr  = (m & 3) * S_ + (m >> 2);
                int pr8 = pr + 2;   // (m+8): same b, s+2
                *(__nv_bfloat162*)&outH[(size_t)pr  * ldc + n] = __floats2bfloat162_rn(v0, v1);
                *(__nv_bfloat162*)&outH[(size_t)pr8 * ldc + n] = __floats2bfloat162_rn(v2, v3);
                rsum0 += v0*v0 + v1*v1; rsum1 += v2*v2 + v3*v3;
            } else if (EP == 2) {
                float b0v = bias[n], b1v = bias[n+1];
                v0 = fmaxf(v0 + b0v, 0.f); v1 = fmaxf(v1 + b1v, 0.f);
                v2 = fmaxf(v2 + b0v, 0.f); v3 = fmaxf(v3 + b1v, 0.f);
                __nv_bfloat162 h01 = __floats2bfloat162_rn(v0, v1);
                __nv_bfloat162 h23 = __floats2bfloat162_rn(v2, v3);
                float2 f01 = __bfloat1622float2(h01);
                float2 f23 = __bfloat1622float2(h23);
                __nv_bfloat162 l01 = __floats2bfloat162_rn(v0 - f01.x, v1 - f01.y);
                __nv_bfloat162 l23 = __floats2bfloat162_rn(v2 - f23.x, v3 - f23.y);
                *(__nv_bfloat162*)&outH[(size_t)m * ldc + n]            = h01;
                *(__nv_bfloat162*)&outH[(size_t)m * ldc + n + 1024]     = h01;
                *(__nv_bfloat162*)&outH[(size_t)m * ldc + n + 2048]     = l01;
                *(__nv_bfloat162*)&outH[(size_t)(m+8) * ldc + n]        = h23;
                *(__nv_bfloat162*)&outH[(size_t)(m+8) * ldc + n + 1024] = h23;
                *(__nv_bfloat162*)&outH[(size_t)(m+8) * ldc + n + 2048] = l23;
            } else {
                float b0v = bias[n], b1v = bias[n+1];
                *(float2*)&outF[(size_t)m * ldc + n]     = make_float2(v0 + b0v, v1 + b1v);
                *(float2*)&outF[(size_t)(m+8) * ldc + n] = make_float2(v2 + b0v, v3 + b1v);
            }
        }
        if (EP == 1 || EP == 4) {
            rsum0 += __shfl_xor_sync(0xffffffffu, rsum0, 1);
            rsum0 += __shfl_xor_sync(0xffffffffu, rsum0, 2);
            rsum1 += __shfl_xor_sync(0xffffffffu, rsum1, 1);
            rsum1 += __shfl_xor_sync(0xffffffffu, rsum1, 2);
            if ((lane & 3) == 0) {
                if (EP == 1) {
                    atomicAdd(&rowsum[m], rsum0);
                    atomicAdd(&rowsum[m + 8], rsum1);
                } else {
                    int pr = (m & 3) * S_ + (m >> 2);
                    atomicAdd(&rowsum[pr], rsum0);
                    atomicAdd(&rowsum[pr + 2], rsum1);
                }
            }
        }
    }
}

// ---------------- GEMM wrappers ----------------
__global__ void __launch_bounds__(256) k_proj() {
    int z = blockIdx.z; int h = z & 3; int sel = z >> 2;
    const bf16* A = sel ? g_memb : g_srcb;
    const bf16* W = (sel ? g_WQb : g_WKb) + (size_t)h * K_ * D_;
    bf16* C = (sel ? g_wqh : g_wkh) + (size_t)h * SB_ * K_;     // [h][b][s][k]
    float* ss = (sel ? g_ssq : g_ssk) + h * SB_;                // [h][b*S+s]
    mma_core<4>(A, D_, W, D_, D_, blockIdx.y*128, blockIdx.x*128,
                nullptr, C, K_, nullptr, ss, nullptr, nullptr, nullptr);
}

__global__ void __launch_bounds__(256) k_gram() {
    int z = blockIdx.z; int h = z >> 2, b = z & 3;
    const bf16* A  = g_wqh + (size_t)(h * B_ + b) * S_ * K_;
    const bf16* Bm = g_wkh + (size_t)(h * B_ + b) * S_ * K_;
    const float* iq = g_ssq + (h * B_ + b) * S_;
    const float* ik = g_ssk + (h * B_ + b) * S_;
    bf16* C = g_P + (size_t)z * S_ * S_;
    mma_core<1>(A, K_, Bm, K_, K_, blockIdx.y*128, blockIdx.x*128,
                nullptr, C, S_, nullptr, g_rowsum + z * S_, g_P0 + z * S_, iq, ik);
}

__global__ void __launch_bounds__(256) k_ffn1(const float* __restrict__ l1b) {
    mma_core<2>(g_xs, 3*D_, g_l1ws, 3*D_, 3*D_, blockIdx.y*128, blockIdx.x*128,
                nullptr, g_h1s, 3*FF_, l1b, nullptr, nullptr, nullptr, nullptr);
}

__global__ void __launch_bounds__(256) k_ffn2(const float* __restrict__ l2b) {
    mma_core<3>(g_h1s, 3*FF_, g_l2ws, 3*FF_, 3*FF_, blockIdx.y*128, blockIdx.x*128,
                g_ff, nullptr, D_, l2b, nullptr, nullptr, nullptr, nullptr);
}

// ---------------- elementwise / reduction kernels ----------------
__global__ void k_cvt(const float* __restrict__ src, int which, int n) {
    bf16* dst;
    switch (which) {
        case 0: dst = g_srcb; break;
        case 1: dst = g_memb; break;
        case 2: dst = g_WKb;  break;
        default: dst = g_WQb; break;
    }
    int i = blockIdx.x * 256 + threadIdx.x;
    if (i * 4 < n) {
        float4 v = *(const float4*)(src + i*4);
        ((__nv_bfloat162*)dst)[i*2]   = __floats2bfloat162_rn(v.x, v.y);
        ((__nv_bfloat162*)dst)[i*2+1] = __floats2bfloat162_rn(v.z, v.w);
    }
}

__global__ void k_wsplit(const float* __restrict__ src, int which) {
    int len = which == 0 ? D_ : FF_;
    bf16* dst = which == 0 ? g_l1ws : g_l2ws;
    int i = blockIdx.x * 256 + threadIdx.x;
    int row = i / len, c = i % len;
    float v = src[i];
    bf16 hi = __float2bfloat16(v);
    bf16 lo = __float2bfloat16(v - __bfloat162float(hi));
    size_t base = (size_t)row * 3 * len;
    dst[base + c] = hi;
    dst[base + len + c] = lo;
    dst[base + 2*len + c] = hi;
}

__global__ void k_zero3() {
    int i = blockIdx.x * 256 + threadIdx.x;
    if (i < ZB_*S_) {
        g_rowsum[i] = 0.f; g_colsum[i] = 0.f;
        g_ssq[i] = 0.f;    g_ssk[i] = 0.f;      // NH_*SB_ == ZB_*S_
    }
    if (i < ZB_*D_) g_ctx[i] = 0.f;
}

// invn = 1 / max(sqrt(ss), 1e-12), in place on g_ssq / g_ssk
__global__ void k_invn() {
    int i = blockIdx.x * 256 + threadIdx.x;
    float* a = (i < NH_*SB_) ? g_ssq : g_ssk;
    int j = (i < NH_*SB_) ? i : i - NH_*SB_;
    a[j] = 1.f / fmaxf(sqrtf(a[j]), 1e-12f);
}

// colsum over bf16 P: grid (S/256, ZB, S/128); inv computed inline
__global__ void k_colsum() {
    __shared__ float sinv[128];
    int z = blockIdx.y, qb = blockIdx.z;
    int t = threadIdx.x;
    if (t < 128) sinv[t] = 1.f / g_rowsum[z*S_ + qb*128 + t];
    __syncthreads();
    int s = blockIdx.x * 256 + t;
    const bf16* P = g_P + (size_t)z*S_*S_ + (size_t)qb*128*S_ + s;
    float cs = 0.f;
#pragma unroll 4
    for (int q = 0; q < 128; q++)
        cs = fmaf(__bfloat162float(P[(size_t)q * S_]), sinv[q], cs);
    atomicAdd(&g_colsum[z*S_ + s], cs);
}

__global__ void k_aff0() {
    int i = blockIdx.x * 256 + threadIdx.x;   // z*S + s
    int z = i >> 11;
    float a0 = g_P0[i] / g_rowsum[z*S_];
    g_aff0[i] = a0 / (1e-9f + g_colsum[i]);
}

__global__ void k_ctx(const float* __restrict__ srcc) {
    int z = blockIdx.y; int b = z & 3;
    int d = threadIdx.x;
    int s0 = blockIdx.x * 256;
    float acc = 0.f;
    for (int si = 0; si < 256; si++) {
        int s = s0 + si;
        acc = fmaf(g_aff0[z*S_ + s], srcc[((size_t)s*B_ + b)*D_ + d], acc);
    }
    atomicAdd(&g_ctx[z*D_ + d], acc);
}

__global__ void k_head(const float* __restrict__ memory,
                       const float* __restrict__ WV, const float* __restrict__ Wt,
                       const float* __restrict__ e1w, const float* __restrict__ e1b,
                       const float* __restrict__ e2w, const float* __restrict__ e2b,
                       const float* __restrict__ eg,  const float* __restrict__ eb)
{
    __shared__ float cx[256], tv[256], rus[256], hm[1024], red[8];
    int z = blockIdx.x; int h = z >> 2, b = z & 3;
    int t = threadIdx.x;
    cx[t] = g_ctx[z*D_ + t];
    __syncthreads();

    const float* wv = WV + ((size_t)h*D_ + t) * D_;
    float o = 0.f;
#pragma unroll 4
    for (int d = 0; d < D_; d++) o = fmaf(wv[d], cx[d], o);
    tv[t] = memory[(size_t)b * D_ + t] - o;
    __syncthreads();

    const float* wt = Wt + ((size_t)h*D_ + t) * D_;
    float r = 0.f;
#pragma unroll 4
    for (int d = 0; d < D_; d++) r = fmaf(wt[d], tv[d], r);
    rus[t] = fmaxf(r, 0.f);
    __syncthreads();

#pragma unroll
    for (int i = 0; i < 4; i++) {
        int kx = i*256 + t;
        const float* w = e1w + ((size_t)h*K_ + kx) * D_;
        float v = e1b[h*K_ + kx];
#pragma unroll 4
        for (int d = 0; d < D_; d++) v = fmaf(w[d], rus[d], v);
        hm[kx] = fmaxf(v, 0.f);
    }
    __syncthreads();

    const float* w2 = e2w + ((size_t)h*D_ + t) * K_;
    float s2 = e2b[h*D_ + t];
#pragma unroll 4
    for (int kx = 0; kx < K_; kx++) s2 = fmaf(w2[kx], hm[kx], s2);

    float v = rus[t] + s2;
    g_xh[z*D_ + t] = ln256(v, eg[h*D_ + t], eb[h*D_ + t], red);
}

__global__ void k_out0(const float* __restrict__ Wout) {
    __shared__ float cat[1024];
    int b = blockIdx.x, d = threadIdx.x;
#pragma unroll
    for (int i = 0; i < 4; i++) cat[i*256 + d] = g_xh[(i*B_ + b)*D_ + d];
    __syncthreads();
    const float* w = Wout + (size_t)d * 1024;
    float acc = 0.f;
#pragma unroll 4
    for (int k = 0; k < 1024; k++) acc = fmaf(w[k], cat[k], acc);
    g_src2[b*D_ + d] = acc;
}

__global__ void k_ln1(const float* __restrict__ memory,
                      const float* __restrict__ n1g, const float* __restrict__ n1b) {
    __shared__ float red[8];
    int sb = blockIdx.x; int b = sb & 3; int t = threadIdx.x;
    float v = memory[(size_t)sb*D_ + t] + g_src2[b*D_ + t];
    float x = ln256(v, n1g[t], n1b[t], red);
    g_x[(size_t)sb*D_ + t] = x;
    bf16 hi = __float2bfloat16(x);
    bf16 lo = __float2bfloat16(x - __bfloat162float(hi));
    size_t base = (size_t)sb * 3 * D_;
    g_xs[base + t] = hi;
    g_xs[base + D_ + t] = hi;
    g_xs[base + 2*D_ + t] = lo;
}

__global__ void k_ln3(const float* __restrict__ n3g, const float* __restrict__ n3b,
                      float* __restrict__ out) {
    __shared__ float red[8];
    int sb = blockIdx.x; int t = threadIdx.x;
    float v = g_x[(size_t)sb*D_ + t] + g_ff[(size_t)sb*D_ + t];
    out[(size_t)sb*D_ + t] = ln256(v, n3g[t], n3b[t], red);
}

// ---------------- launch ----------------
extern "C" void kernel_launch(void* const* d_in, const int* in_sizes, int n_in,
                              void* d_out, int out_size) {
    (void)in_sizes; (void)n_in; (void)out_size;
    const float* srcc   = (const float*)d_in[0];
    const float* memory = (const float*)d_in[1];
    const float* WV   = (const float*)d_in[4];
    const float* Wt   = (const float*)d_in[5];
    const float* e1w  = (const float*)d_in[6];
    const float* e1b  = (const float*)d_in[7];
    const float* e2w  = (const float*)d_in[8];
    const float* e2b  = (const float*)d_in[9];
    const float* eg   = (const float*)d_in[10];
    const float* eb   = (const float*)d_in[11];
    const float* Wout = (const float*)d_in[12];
    const float* l1w  = (const float*)d_in[13];
    const float* l1b  = (const float*)d_in[14];
    const float* l2w  = (const float*)d_in[15];
    const float* l2b  = (const float*)d_in[16];
    const float* n1g  = (const float*)d_in[17];
    const float* n1b  = (const float*)d_in[18];
    const float* n3g  = (const float*)d_in[19];
    const float* n3b  = (const float*)d_in[20];
    float* out = (float*)d_out;

    k_zero3<<<(ZB_*S_ + 255)/256, 256>>>();
    k_cvt<<<SB_*D_/1024, 256>>>(srcc,   0, SB_*D_);
    k_cvt<<<SB_*D_/1024, 256>>>(memory, 1, SB_*D_);
    k_cvt<<<NH_*K_*D_/1024, 256>>>((const float*)d_in[2], 2, NH_*K_*D_);
    k_cvt<<<NH_*K_*D_/1024, 256>>>((const float*)d_in[3], 3, NH_*K_*D_);
    k_wsplit<<<FF_*D_/256, 256>>>(l1w, 0);
    k_wsplit<<<D_*FF_/256, 256>>>(l2w, 1);

    k_proj  <<<dim3(K_/128, SB_/128, 8), 256>>>();
    k_invn  <<<2*NH_*SB_/256, 256>>>();
    k_gram  <<<dim3(S_/128, S_/128, ZB_), 256>>>();
    k_colsum<<<dim3(S_/256, ZB_, S_/128), 256>>>();
    k_aff0  <<<ZB_*S_/256, 256>>>();
    k_ctx   <<<dim3(S_/256, ZB_), 256>>>(srcc);
    k_head  <<<ZB_, 256>>>(memory, WV, Wt, e1w, e1b, e2w, e2b, eg, eb);
    k_out0  <<<B_, 256>>>(Wout);
    k_ln1   <<<SB_, 256>>>(memory, n1g, n1b);
    k_ffn1  <<<dim3(FF_/128, SB_/128), 256>>>(l1b);
    k_ffn2  <<<dim3(D_/128, SB_/128), 256>>>(l2b);
    k_ln3   <<<SB_, 256>>>(n3g, n3b, out);
}

// round 13
// speedup vs baseline: 1.5227x; 1.2684x over previous
#include <cuda_runtime.h>
#include <cuda_bf16.h>
#include <cstdint>

typedef __nv_bfloat16 bf16;

#define S_  2048
#define B_  4
#define D_  256
#define NH_ 4
#define K_  1024
#define FF_ 1024
#define SB_ (S_*B_)
#define ZB_ (NH_*B_)

// ---------------- scratch ----------------
// wq/wk stored UNNORMALIZED in [h][b][s][k] layout (lda = K_)
static __device__ __align__(16) bf16  g_wqh[(size_t)NH_*SB_*K_];   // 64 MB
static __device__ __align__(16) bf16  g_wkh[(size_t)NH_*SB_*K_];   // 64 MB
static __device__ __align__(16) bf16  g_P  [(size_t)ZB_*S_*S_];    // 128 MB exp(dot) bf16
static __device__ float g_P0 [ZB_*S_];                             // exact row q=0
static __device__ float g_ssq[NH_*SB_];   // sum-of-squares -> inv norm (wq)
static __device__ float g_ssk[NH_*SB_];   // same for wk
static __device__ float g_rowsum[ZB_*S_];
static __device__ float g_colsum[ZB_*S_];
static __device__ float g_aff0  [ZB_*S_];
static __device__ float g_ctx[ZB_*D_];
static __device__ float g_rus[ZB_*D_];
static __device__ float g_hm [ZB_*K_];
static __device__ float g_s2 [ZB_*D_];
static __device__ float g_xh [ZB_*D_];
static __device__ float g_src2[B_*D_];
static __device__ __align__(16) float g_x  [SB_*D_];
static __device__ __align__(16) float g_ff [SB_*D_];
// split-bf16 FFN operands:  A' = [hi|hi|lo],  B' = [hi|lo|hi]
static __device__ __align__(16) bf16 g_xs  [(size_t)SB_*3*D_];
static __device__ __align__(16) bf16 g_h1s [(size_t)SB_*3*FF_];
static __device__ __align__(16) bf16 g_l1ws[(size_t)FF_*3*D_];
static __device__ __align__(16) bf16 g_l2ws[(size_t)D_*3*FF_];
// bf16 copies of inputs (attention path)
static __device__ __align__(16) bf16 g_srcb[SB_*D_];
static __device__ __align__(16) bf16 g_memb[SB_*D_];
static __device__ __align__(16) bf16 g_WKb [NH_*K_*D_];
static __device__ __align__(16) bf16 g_WQb [NH_*K_*D_];

// ---------------- small helpers ----------------
__device__ __forceinline__ float blk_sum(float v, float* red, int nw) {
#pragma unroll
    for (int o = 16; o > 0; o >>= 1) v += __shfl_xor_sync(0xffffffffu, v, o);
    int w = threadIdx.x >> 5;
    if ((threadIdx.x & 31) == 0) red[w] = v;
    __syncthreads();
    float s = 0.f;
    for (int i = 0; i < nw; i++) s += red[i];
    __syncthreads();
    return s;
}
__device__ __forceinline__ float ln256(float v, float g, float b, float* red) {
    float mean = blk_sum(v, red, 8) * (1.f/256.f);
    float dv = v - mean;
    float var = blk_sum(dv*dv, red, 8) * (1.f/256.f);
    return dv * rsqrtf(var + 1e-5f) * g + b;
}
__device__ __forceinline__ unsigned sa(const void* p) {
    return (unsigned)__cvta_generic_to_shared(p);
}
// exp(x) for x in [-1.05, 1.05]: degree-9 Taylor, rel err < 3e-6, all FMA-pipe
__device__ __forceinline__ float expp(float x) {
    float r = 2.7557319e-6f;
    r = fmaf(r, x, 2.4801587e-5f);
    r = fmaf(r, x, 1.9841270e-4f);
    r = fmaf(r, x, 1.3888889e-3f);
    r = fmaf(r, x, 8.3333333e-3f);
    r = fmaf(r, x, 4.1666667e-2f);
    r = fmaf(r, x, 1.6666667e-1f);
    r = fmaf(r, x, 0.5f);
    r = fmaf(r, x, 1.0f);
    r = fmaf(r, x, 1.0f);
    return r;
}

// ---------------- bf16 HMMA GEMM core (R5 structure) ----------------
// EP: 1 scale(invq,invk)+exp(poly)->bf16 P + f32 row0 + rowsum atomics,
//     2 relu+bias -> split triple bf16, 3 bias -> f32,
//     4 proj: bf16 raw to PERMUTED rows ((m&3)*S+(m>>2)) + sum-of-squares atomics
template<int EP>
__device__ __forceinline__ void mma_core(
    const bf16* __restrict__ A, int lda,
    const bf16* __restrict__ Bw, int ldb,
    int Kd, int m0, int n0,
    float* __restrict__ outF, bf16* __restrict__ outH, int ldc,
    const float* __restrict__ bias, float* __restrict__ rowsum, float* __restrict__ p0,
    const float* __restrict__ invq, const float* __restrict__ invk)
{
    __shared__ __align__(16) bf16 As[2][128][40];
    __shared__ __align__(16) bf16 Bs[2][128][40];

    const int tid  = threadIdx.x;
    const int lane = tid & 31;
    const int wid  = tid >> 5;
    const int wm0  = (wid & 1) * 64;
    const int wn0  = (wid >> 1) * 32;

    const int c0 = tid, c1 = tid + 256;
    const int ar0 = c0 >> 2, ak0 = (c0 & 3) * 8;
    const int ar1 = c1 >> 2, ak1 = (c1 & 3) * 8;

    float acc[4][4][4];
#pragma unroll
    for (int i = 0; i < 4; i++)
#pragma unroll
        for (int j = 0; j < 4; j++)
#pragma unroll
            for (int k = 0; k < 4; k++) acc[i][j][k] = 0.f;

    const int nK = Kd >> 5;

    {
        const bf16* a0 = A  + (size_t)(m0 + ar0) * lda + ak0;
        const bf16* a1 = A  + (size_t)(m0 + ar1) * lda + ak1;
        const bf16* b0 = Bw + (size_t)(n0 + ar0) * ldb + ak0;
        const bf16* b1 = Bw + (size_t)(n0 + ar1) * ldb + ak1;
        asm volatile("cp.async.cg.shared.global [%0],[%1],16;\n"::"r"(sa(&As[0][ar0][ak0])),"l"(a0));
        asm volatile("cp.async.cg.shared.global [%0],[%1],16;\n"::"r"(sa(&As[0][ar1][ak1])),"l"(a1));
        asm volatile("cp.async.cg.shared.global [%0],[%1],16;\n"::"r"(sa(&Bs[0][ar0][ak0])),"l"(b0));
        asm volatile("cp.async.cg.shared.global [%0],[%1],16;\n"::"r"(sa(&Bs[0][ar1][ak1])),"l"(b1));
        asm volatile("cp.async.commit_group;\n");
    }

    for (int kb = 0; kb < nK; kb++) {
        asm volatile("cp.async.wait_group 0;\n");
        __syncthreads();
        if (kb + 1 < nK) {
            int st = (kb + 1) & 1;
            int ko = (kb + 1) * 32;
            const bf16* a0 = A  + (size_t)(m0 + ar0) * lda + ko + ak0;
            const bf16* a1 = A  + (size_t)(m0 + ar1) * lda + ko + ak1;
            const bf16* b0 = Bw + (size_t)(n0 + ar0) * ldb + ko + ak0;
            const bf16* b1 = Bw + (size_t)(n0 + ar1) * ldb + ko + ak1;
            asm volatile("cp.async.cg.shared.global [%0],[%1],16;\n"::"r"(sa(&As[st][ar0][ak0])),"l"(a0));
            asm volatile("cp.async.cg.shared.global [%0],[%1],16;\n"::"r"(sa(&As[st][ar1][ak1])),"l"(a1));
            asm volatile("cp.async.cg.shared.global [%0],[%1],16;\n"::"r"(sa(&Bs[st][ar0][ak0])),"l"(b0));
            asm volatile("cp.async.cg.shared.global [%0],[%1],16;\n"::"r"(sa(&Bs[st][ar1][ak1])),"l"(b1));
            asm volatile("cp.async.commit_group;\n");
        }
        int st = kb & 1;
#pragma unroll
        for (int ks = 0; ks < 2; ks++) {
            unsigned a[4][4];
            unsigned bfr[4][2];
#pragma unroll
            for (int mt = 0; mt < 4; mt++) {
                unsigned ad = sa(&As[st][wm0 + mt*16 + (lane & 15)][ks*16 + (lane >> 4)*8]);
                asm volatile("ldmatrix.sync.aligned.m8n8.x4.shared.b16 {%0,%1,%2,%3},[%4];\n"
                    : "=r"(a[mt][0]), "=r"(a[mt][1]), "=r"(a[mt][2]), "=r"(a[mt][3]) : "r"(ad));
            }
#pragma unroll
            for (int bp = 0; bp < 2; bp++) {
                unsigned r0, r1, r2, r3;
                unsigned ad = sa(&Bs[st][wn0 + bp*16 + (lane & 15)][ks*16 + (lane >> 4)*8]);
                asm volatile("ldmatrix.sync.aligned.m8n8.x4.shared.b16 {%0,%1,%2,%3},[%4];\n"
                    : "=r"(r0), "=r"(r1), "=r"(r2), "=r"(r3) : "r"(ad));
                bfr[bp*2  ][0] = r0; bfr[bp*2  ][1] = r2;
                bfr[bp*2+1][0] = r1; bfr[bp*2+1][1] = r3;
            }
#pragma unroll
            for (int mt = 0; mt < 4; mt++)
#pragma unroll
                for (int nt = 0; nt < 4; nt++) {
                    asm volatile(
                        "mma.sync.aligned.m16n8k16.row.col.f32.bf16.bf16.f32 "
                        "{%0,%1,%2,%3},{%4,%5,%6,%7},{%8,%9},{%0,%1,%2,%3};\n"
                        : "+f"(acc[mt][nt][0]), "+f"(acc[mt][nt][1]),
                          "+f"(acc[mt][nt][2]), "+f"(acc[mt][nt][3])
                        : "r"(a[mt][0]), "r"(a[mt][1]), "r"(a[mt][2]), "r"(a[mt][3]),
                          "r"(bfr[nt][0]), "r"(bfr[nt][1]));
                }
        }
        __syncthreads();
    }

    // ---------------- epilogue ----------------
    const int er = lane >> 2;
    const int ec = (lane & 3) * 2;
#pragma unroll
    for (int mt = 0; mt < 4; mt++) {
        float rsum0 = 0.f, rsum1 = 0.f;
        const int m = m0 + wm0 + mt*16 + er;
        float iq0 = 0.f, iq1 = 0.f;
        if (EP == 1) { iq0 = invq[m]; iq1 = invq[m + 8]; }
#pragma unroll
        for (int nt = 0; nt < 4; nt++) {
            int n = n0 + wn0 + nt*8 + ec;
            float v0 = acc[mt][nt][0], v1 = acc[mt][nt][1];
            float v2 = acc[mt][nt][2], v3 = acc[mt][nt][3];
            if (EP == 1) {
                float ik0 = invk[n], ik1 = invk[n+1];
                v0 = expp(v0 * iq0 * ik0); v1 = expp(v1 * iq0 * ik1);
                v2 = expp(v2 * iq1 * ik0); v3 = expp(v3 * iq1 * ik1);
                rsum0 += v0 + v1; rsum1 += v2 + v3;
                *(__nv_bfloat162*)&outH[(size_t)m * ldc + n]     = __floats2bfloat162_rn(v0, v1);
                *(__nv_bfloat162*)&outH[(size_t)(m+8) * ldc + n] = __floats2bfloat162_rn(v2, v3);
                if (m == 0) { p0[n] = v0; p0[n+1] = v1; }   // exact row q=0
            } else if (EP == 4) {
                int pr  = (m & 3) * S_ + (m >> 2);
                int pr8 = pr + 2;   // (m+8): same b, s+2
                *(__nv_bfloat162*)&outH[(size_t)pr  * ldc + n] = __floats2bfloat162_rn(v0, v1);
                *(__nv_bfloat162*)&outH[(size_t)pr8 * ldc + n] = __floats2bfloat162_rn(v2, v3);
                rsum0 += v0*v0 + v1*v1; rsum1 += v2*v2 + v3*v3;
            } else if (EP == 2) {
                float b0v = bias[n], b1v = bias[n+1];
                v0 = fmaxf(v0 + b0v, 0.f); v1 = fmaxf(v1 + b1v, 0.f);
                v2 = fmaxf(v2 + b0v, 0.f); v3 = fmaxf(v3 + b1v, 0.f);
                __nv_bfloat162 h01 = __floats2bfloat162_rn(v0, v1);
                __nv_bfloat162 h23 = __floats2bfloat162_rn(v2, v3);
                float2 f01 = __bfloat1622float2(h01);
                float2 f23 = __bfloat1622float2(h23);
                __nv_bfloat162 l01 = __floats2bfloat162_rn(v0 - f01.x, v1 - f01.y);
                __nv_bfloat162 l23 = __floats2bfloat162_rn(v2 - f23.x, v3 - f23.y);
                *(__nv_bfloat162*)&outH[(size_t)m * ldc + n]            = h01;
                *(__nv_bfloat162*)&outH[(size_t)m * ldc + n + 1024]     = h01;
                *(__nv_bfloat162*)&outH[(size_t)m * ldc + n + 2048]     = l01;
                *(__nv_bfloat162*)&outH[(size_t)(m+8) * ldc + n]        = h23;
                *(__nv_bfloat162*)&outH[(size_t)(m+8) * ldc + n + 1024] = h23;
                *(__nv_bfloat162*)&outH[(size_t)(m+8) * ldc + n + 2048] = l23;
            } else {
                float b0v = bias[n], b1v = bias[n+1];
                *(float2*)&outF[(size_t)m * ldc + n]     = make_float2(v0 + b0v, v1 + b1v);
                *(float2*)&outF[(size_t)(m+8) * ldc + n] = make_float2(v2 + b0v, v3 + b1v);
            }
        }
        if (EP == 1 || EP == 4) {
            rsum0 += __shfl_xor_sync(0xffffffffu, rsum0, 1);
            rsum0 += __shfl_xor_sync(0xffffffffu, rsum0, 2);
            rsum1 += __shfl_xor_sync(0xffffffffu, rsum1, 1);
            rsum1 += __shfl_xor_sync(0xffffffffu, rsum1, 2);
            if ((lane & 3) == 0) {
                if (EP == 1) {
                    atomicAdd(&rowsum[m], rsum0);
                    atomicAdd(&rowsum[m + 8], rsum1);
                } else {
                    int pr = (m & 3) * S_ + (m >> 2);
                    atomicAdd(&rowsum[pr], rsum0);
                    atomicAdd(&rowsum[pr + 2], rsum1);
                }
            }
        }
    }
}

// ---------------- GEMM wrappers ----------------
__global__ void __launch_bounds__(256) k_proj() {
    int z = blockIdx.z; int h = z & 3; int sel = z >> 2;
    const bf16* A = sel ? g_memb : g_srcb;
    const bf16* W = (sel ? g_WQb : g_WKb) + (size_t)h * K_ * D_;
    bf16* C = (sel ? g_wqh : g_wkh) + (size_t)h * SB_ * K_;     // [h][b][s][k]
    float* ss = (sel ? g_ssq : g_ssk) + h * SB_;                // [h][b*S+s]
    mma_core<4>(A, D_, W, D_, D_, blockIdx.y*128, blockIdx.x*128,
                nullptr, C, K_, nullptr, ss, nullptr, nullptr, nullptr);
}

__global__ void __launch_bounds__(256) k_gram() {
    int z = blockIdx.z; int h = z >> 2, b = z & 3;
    const bf16* A  = g_wqh + (size_t)(h * B_ + b) * S_ * K_;
    const bf16* Bm = g_wkh + (size_t)(h * B_ + b) * S_ * K_;
    const float* iq = g_ssq + (h * B_ + b) * S_;
    const float* ik = g_ssk + (h * B_ + b) * S_;
    bf16* C = g_P + (size_t)z * S_ * S_;
    mma_core<1>(A, K_, Bm, K_, K_, blockIdx.y*128, blockIdx.x*128,
                nullptr, C, S_, nullptr, g_rowsum + z * S_, g_P0 + z * S_, iq, ik);
}

__global__ void __launch_bounds__(256) k_ffn1(const float* __restrict__ l1b) {
    mma_core<2>(g_xs, 3*D_, g_l1ws, 3*D_, 3*D_, blockIdx.y*128, blockIdx.x*128,
                nullptr, g_h1s, 3*FF_, l1b, nullptr, nullptr, nullptr, nullptr);
}

__global__ void __launch_bounds__(256) k_ffn2(const float* __restrict__ l2b) {
    mma_core<3>(g_h1s, 3*FF_, g_l2ws, 3*FF_, 3*FF_, blockIdx.y*128, blockIdx.x*128,
                g_ff, nullptr, D_, l2b, nullptr, nullptr, nullptr, nullptr);
}

// ---------------- elementwise / reduction kernels ----------------
// all four bf16 conversions in one launch (vec4 index space)
#define CV0 (SB_*D_/4)
#define CV1 (2*CV0)
#define CV2 (CV1 + NH_*K_*D_/4)
#define CV3 (CV2 + NH_*K_*D_/4)
__global__ void k_cvt_all(const float* __restrict__ srcc, const float* __restrict__ mem,
                          const float* __restrict__ WK, const float* __restrict__ WQ) {
    int i = blockIdx.x * 256 + threadIdx.x;
    if (i >= CV3) return;
    const float* s; bf16* d; int off;
    if (i < CV0)      { s = srcc; d = g_srcb; off = i; }
    else if (i < CV1) { s = mem;  d = g_memb; off = i - CV0; }
    else if (i < CV2) { s = WK;   d = g_WKb;  off = i - CV1; }
    else              { s = WQ;   d = g_WQb;  off = i - CV2; }
    float4 v = ((const float4*)s)[off];
    ((__nv_bfloat162*)d)[off*2]   = __floats2bfloat162_rn(v.x, v.y);
    ((__nv_bfloat162*)d)[off*2+1] = __floats2bfloat162_rn(v.z, v.w);
}

__global__ void k_wsplit(const float* __restrict__ src, int which) {
    int len = which == 0 ? D_ : FF_;
    bf16* dst = which == 0 ? g_l1ws : g_l2ws;
    int i = blockIdx.x * 256 + threadIdx.x;
    int row = i / len, c = i % len;
    float v = src[i];
    bf16 hi = __float2bfloat16(v);
    bf16 lo = __float2bfloat16(v - __bfloat162float(hi));
    size_t base = (size_t)row * 3 * len;
    dst[base + c] = hi;
    dst[base + len + c] = lo;
    dst[base + 2*len + c] = hi;
}

__global__ void k_zero3() {
    int i = blockIdx.x * 256 + threadIdx.x;
    if (i < ZB_*S_) {
        g_rowsum[i] = 0.f; g_colsum[i] = 0.f;
        g_ssq[i] = 0.f;    g_ssk[i] = 0.f;
    }
    if (i < ZB_*D_) { g_ctx[i] = 0.f; g_s2[i] = 0.f; }
    if (i < B_*D_)  g_src2[i] = 0.f;
}

// invn = 1 / max(sqrt(ss), 1e-12), in place on g_ssq / g_ssk
__global__ void k_invn() {
    int i = blockIdx.x * 256 + threadIdx.x;
    float* a = (i < NH_*SB_) ? g_ssq : g_ssk;
    int j = (i < NH_*SB_) ? i : i - NH_*SB_;
    a[j] = 1.f / fmaxf(sqrtf(a[j]), 1e-12f);
}

// colsum over bf16 P: grid (S/256, ZB, S/128); inv computed inline
__global__ void k_colsum() {
    __shared__ float sinv[128];
    int z = blockIdx.y, qb = blockIdx.z;
    int t = threadIdx.x;
    if (t < 128) sinv[t] = 1.f / g_rowsum[z*S_ + qb*128 + t];
    __syncthreads();
    int s = blockIdx.x * 256 + t;
    const bf16* P = g_P + (size_t)z*S_*S_ + (size_t)qb*128*S_ + s;
    float cs = 0.f;
#pragma unroll 4
    for (int q = 0; q < 128; q++)
        cs = fmaf(__bfloat162float(P[(size_t)q * S_]), sinv[q], cs);
    atomicAdd(&g_colsum[z*S_ + s], cs);
}

__global__ void k_aff0() {
    int i = blockIdx.x * 256 + threadIdx.x;   // z*S + s
    int z = i >> 11;
    float a0 = g_P0[i] / g_rowsum[z*S_];
    g_aff0[i] = a0 / (1e-9f + g_colsum[i]);
}

__global__ void k_ctx(const float* __restrict__ srcc) {
    int z = blockIdx.y; int b = z & 3;
    int d = threadIdx.x;
    int s0 = blockIdx.x * 256;
    float acc = 0.f;
    for (int si = 0; si < 256; si++) {
        int s = s0 + si;
        acc = fmaf(g_aff0[z*S_ + s], srcc[((size_t)s*B_ + b)*D_ + d], acc);
    }
    atomicAdd(&g_ctx[z*D_ + d], acc);
}

// ---------------- per-head chain, split for parallelism ----------------
// A: o = WV@ctx; tv = memory0 - o; rus = relu(Wt@tv)          grid ZB_
__global__ void k_headA(const float* __restrict__ memory,
                        const float* __restrict__ WV, const float* __restrict__ Wt) {
    __shared__ float cx[256], tv[256];
    int z = blockIdx.x; int h = z >> 2, b = z & 3;
    int t = threadIdx.x;
    cx[t] = g_ctx[z*D_ + t];
    __syncthreads();
    const float* wv = WV + ((size_t)h*D_ + t) * D_;
    float o = 0.f;
#pragma unroll 4
    for (int d = 0; d < D_; d++) o = fmaf(wv[d], cx[d], o);
    tv[t] = memory[(size_t)b * D_ + t] - o;
    __syncthreads();
    const float* wt = Wt + ((size_t)h*D_ + t) * D_;
    float r = 0.f;
#pragma unroll 4
    for (int d = 0; d < D_; d++) r = fmaf(wt[d], tv[d], r);
    g_rus[z*D_ + t] = fmaxf(r, 0.f);
}

// B: hm[kx] = relu(e1w[h,kx,:]·rus + e1b)                      grid (ZB_, 4)
__global__ void k_headB(const float* __restrict__ e1w, const float* __restrict__ e1b) {
    __shared__ float rus[256];
    int z = blockIdx.x; int h = z >> 2; int j = blockIdx.y;
    int t = threadIdx.x;
    rus[t] = g_rus[z*D_ + t];
    __syncthreads();
    int kx = j * 256 + t;
    const float* w = e1w + ((size_t)h*K_ + kx) * D_;
    float v = e1b[h*K_ + kx];
#pragma unroll 4
    for (int d = 0; d < D_; d++) v = fmaf(w[d], rus[d], v);
    g_hm[z*K_ + kx] = fmaxf(v, 0.f);
}

// C: s2 partial dots over e2w chunks                           grid (ZB_, 4)
__global__ void k_headC(const float* __restrict__ e2w) {
    __shared__ float hm[256];
    int z = blockIdx.x; int h = z >> 2; int j = blockIdx.y;
    int t = threadIdx.x;
    hm[t] = g_hm[z*K_ + j*256 + t];
    __syncthreads();
    const float* w2 = e2w + ((size_t)h*D_ + t) * K_ + j*256;
    float s = 0.f;
#pragma unroll 4
    for (int kx = 0; kx < 256; kx++) s = fmaf(w2[kx], hm[kx], s);
    atomicAdd(&g_s2[z*D_ + t], s);
}

// D: xh = LN(rus + s2 + e2b)                                   grid ZB_
__global__ void k_headD(const float* __restrict__ e2b,
                        const float* __restrict__ eg, const float* __restrict__ eb) {
    __shared__ float red[8];
    int z = blockIdx.x; int h = z >> 2;
    int t = threadIdx.x;
    float v = g_rus[z*D_ + t] + g_s2[z*D_ + t] + e2b[h*D_ + t];
    g_xh[z*D_ + t] = ln256(v, eg[h*D_ + t], eb[h*D_ + t], red);
}

// out0: grid (B_, 4): partial Wout dot over head chunk j
__global__ void k_out0(const float* __restrict__ Wout) {
    __shared__ float cat[256];
    int b = blockIdx.x, j = blockIdx.y, d = threadIdx.x;
    cat[d] = g_xh[(j*B_ + b)*D_ + d];
    __syncthreads();
    const float* w = Wout + (size_t)d * 1024 + j * 256;
    float acc = 0.f;
#pragma unroll 4
    for (int c = 0; c < 256; c++) acc = fmaf(w[c], cat[c], acc);
    atomicAdd(&g_src2[b*D_ + d], acc);
}

__global__ void k_ln1(const float* __restrict__ memory,
                      const float* __restrict__ n1g, const float* __restrict__ n1b) {
    __shared__ float red[8];
    int sb = blockIdx.x; int b = sb & 3; int t = threadIdx.x;
    float v = memory[(size_t)sb*D_ + t] + g_src2[b*D_ + t];
    float x = ln256(v, n1g[t], n1b[t], red);
    g_x[(size_t)sb*D_ + t] = x;
    bf16 hi = __float2bfloat16(x);
    bf16 lo = __float2bfloat16(x - __bfloat162float(hi));
    size_t base = (size_t)sb * 3 * D_;
    g_xs[base + t] = hi;
    g_xs[base + D_ + t] = hi;
    g_xs[base + 2*D_ + t] = lo;
}

__global__ void k_ln3(const float* __restrict__ n3g, const float* __restrict__ n3b,
                      float* __restrict__ out) {
    __shared__ float red[8];
    int sb = blockIdx.x; int t = threadIdx.x;
    float v = g_x[(size_t)sb*D_ + t] + g_ff[(size_t)sb*D_ + t];
    out[(size_t)sb*D_ + t] = ln256(v, n3g[t], n3b[t], red);
}

// ---------------- launch ----------------
extern "C" void kernel_launch(void* const* d_in, const int* in_sizes, int n_in,
                              void* d_out, int out_size) {
    (void)in_sizes; (void)n_in; (void)out_size;
    const float* srcc   = (const float*)d_in[0];
    const float* memory = (const float*)d_in[1];
    const float* WV   = (const float*)d_in[4];
    const float* Wt   = (const float*)d_in[5];
    const float* e1w  = (const float*)d_in[6];
    const float* e1b  = (const float*)d_in[7];
    const float* e2w  = (const float*)d_in[8];
    const float* e2b  = (const float*)d_in[9];
    const float* eg   = (const float*)d_in[10];
    const float* eb   = (const float*)d_in[11];
    const float* Wout = (const float*)d_in[12];
    const float* l1w  = (const float*)d_in[13];
    const float* l1b  = (const float*)d_in[14];
    const float* l2w  = (const float*)d_in[15];
    const float* l2b  = (const float*)d_in[16];
    const float* n1g  = (const float*)d_in[17];
    const float* n1b  = (const float*)d_in[18];
    const float* n3g  = (const float*)d_in[19];
    const float* n3b  = (const float*)d_in[20];
    float* out = (float*)d_out;

    k_zero3<<<(ZB_*S_ + 255)/256, 256>>>();
    k_cvt_all<<<(CV3 + 255)/256, 256>>>(srcc, memory,
                                        (const float*)d_in[2], (const float*)d_in[3]);
    k_wsplit<<<FF_*D_/256, 256>>>(l1w, 0);
    k_wsplit<<<D_*FF_/256, 256>>>(l2w, 1);

    k_proj  <<<dim3(K_/128, SB_/128, 8), 256>>>();
    k_invn  <<<2*NH_*SB_/256, 256>>>();
    k_gram  <<<dim3(S_/128, S_/128, ZB_), 256>>>();
    k_colsum<<<dim3(S_/256, ZB_, S_/128), 256>>>();
    k_aff0  <<<ZB_*S_/256, 256>>>();
    k_ctx   <<<dim3(S_/256, ZB_), 256>>>(srcc);
    k_headA <<<ZB_, 256>>>(memory, WV, Wt);
    k_headB <<<dim3(ZB_, 4), 256>>>(e1w, e1b);
    k_headC <<<dim3(ZB_, 4), 256>>>(e2w);
    k_headD <<<ZB_, 256>>>(e2b, eg, eb);
    k_out0  <<<dim3(B_, 4), 256>>>(Wout);
    k_ln1   <<<SB_, 256>>>(memory, n1g, n1b);
    k_ffn1  <<<dim3(FF_/128, SB_/128), 256>>>(l1b);
    k_ffn2  <<<dim3(D_/128, SB_/128), 256>>>(l2b);
    k_ln3   <<<SB_, 256>>>(n3g, n3b, out);
}

// round 14
// speedup vs baseline: 2.4019x; 1.5774x over previous
#include <cuda_runtime.h>
#include <cuda_bf16.h>
#include <cstdint>

typedef __nv_bfloat16 bf16;

#define S_  2048
#define B_  4
#define D_  256
#define NH_ 4
#define K_  1024
#define FF_ 1024
#define SB_ (S_*B_)
#define ZB_ (NH_*B_)

// ---------------- scratch ----------------
static __device__ __align__(16) bf16  g_u  [(size_t)NH_*SB_*D_];   // 16 MB  u = memory@G^T  [h][s*B+b][d]
static __device__ __align__(16) bf16  g_yq [(size_t)NH_*SB_*D_];   // 16 MB  memory@Mq
static __device__ __align__(16) bf16  g_yk [(size_t)NH_*SB_*D_];   // 16 MB  srcc@Mk
static __device__ __align__(16) bf16  g_GT [NH_*D_*D_];            // G^T per head
static __device__ __align__(16) bf16  g_Mq [NH_*D_*D_];
static __device__ __align__(16) bf16  g_Mk [NH_*D_*D_];
static __device__ __align__(16) bf16  g_WQT[NH_*D_*K_];            // WQ^T bf16 [h][i][k]
static __device__ __align__(16) bf16  g_WKT[NH_*D_*K_];
static __device__ __align__(16) bf16  g_P  [(size_t)ZB_*S_*S_];    // 128 MB exp(dot) bf16
static __device__ float g_P0 [ZB_*S_];                             // exact row q=0
static __device__ float g_ssq[NH_*SB_];   // inv norms (wq) [h][b*S+s]
static __device__ float g_ssk[NH_*SB_];
static __device__ float g_rowsum[ZB_*S_];
static __device__ float g_colsum[ZB_*S_];
static __device__ float g_aff0  [ZB_*S_];
static __device__ float g_ctx[ZB_*D_];
static __device__ float g_rus[ZB_*D_];
static __device__ float g_hm [ZB_*K_];
static __device__ float g_s2 [ZB_*D_];
static __device__ float g_xh [ZB_*D_];
static __device__ float g_src2[B_*D_];
static __device__ __align__(16) float g_x  [SB_*D_];
static __device__ __align__(16) float g_ff [SB_*D_];
// split-bf16 FFN operands
static __device__ __align__(16) bf16 g_xs  [(size_t)SB_*3*D_];
static __device__ __align__(16) bf16 g_h1s [(size_t)SB_*3*FF_];
static __device__ __align__(16) bf16 g_l1ws[(size_t)FF_*3*D_];
static __device__ __align__(16) bf16 g_l2ws[(size_t)D_*3*FF_];
// bf16 copies of inputs
static __device__ __align__(16) bf16 g_srcb[SB_*D_];
static __device__ __align__(16) bf16 g_memb[SB_*D_];

// ---------------- small helpers ----------------
__device__ __forceinline__ float blk_sum(float v, float* red, int nw) {
#pragma unroll
    for (int o = 16; o > 0; o >>= 1) v += __shfl_xor_sync(0xffffffffu, v, o);
    int w = threadIdx.x >> 5;
    if ((threadIdx.x & 31) == 0) red[w] = v;
    __syncthreads();
    float s = 0.f;
    for (int i = 0; i < nw; i++) s += red[i];
    __syncthreads();
    return s;
}
__device__ __forceinline__ float ln256(float v, float g, float b, float* red) {
    float mean = blk_sum(v, red, 8) * (1.f/256.f);
    float dv = v - mean;
    float var = blk_sum(dv*dv, red, 8) * (1.f/256.f);
    return dv * rsqrtf(var + 1e-5f) * g + b;
}
__device__ __forceinline__ unsigned sa(const void* p) {
    return (unsigned)__cvta_generic_to_shared(p);
}
// exp(x) for x in [-1.05, 1.05]: degree-9 Taylor
__device__ __forceinline__ float expp(float x) {
    float r = 2.7557319e-6f;
    r = fmaf(r, x, 2.4801587e-5f);
    r = fmaf(r, x, 1.9841270e-4f);
    r = fmaf(r, x, 1.3888889e-3f);
    r = fmaf(r, x, 8.3333333e-3f);
    r = fmaf(r, x, 4.1666667e-2f);
    r = fmaf(r, x, 1.6666667e-1f);
    r = fmaf(r, x, 0.5f);
    r = fmaf(r, x, 1.0f);
    r = fmaf(r, x, 1.0f);
    return r;
}

// ---------------- bf16 HMMA GEMM core ----------------
// EP: 0 bf16 raw, 1 scale(invq,invk)+exp->bf16 P + f32 row0 + rowsum atomics,
//     2 relu+bias -> split triple bf16, 3 bias -> f32
template<int EP>
__device__ __forceinline__ void mma_core(
    const bf16* __restrict__ A, int lda,
    const bf16* __restrict__ Bw, int ldb,
    int Kd, int m0, int n0,
    float* __restrict__ outF, bf16* __restrict__ outH, int ldc,
    const float* __restrict__ bias, float* __restrict__ rowsum, float* __restrict__ p0,
    const float* __restrict__ invq, const float* __restrict__ invk)
{
    __shared__ __align__(16) bf16 As[2][128][40];
    __shared__ __align__(16) bf16 Bs[2][128][40];

    const int tid  = threadIdx.x;
    const int lane = tid & 31;
    const int wid  = tid >> 5;
    const int wm0  = (wid & 1) * 64;
    const int wn0  = (wid >> 1) * 32;

    const int c0 = tid, c1 = tid + 256;
    const int ar0 = c0 >> 2, ak0 = (c0 & 3) * 8;
    const int ar1 = c1 >> 2, ak1 = (c1 & 3) * 8;

    float acc[4][4][4];
#pragma unroll
    for (int i = 0; i < 4; i++)
#pragma unroll
        for (int j = 0; j < 4; j++)
#pragma unroll
            for (int k = 0; k < 4; k++) acc[i][j][k] = 0.f;

    const int nK = Kd >> 5;

    {
        const bf16* a0 = A  + (size_t)(m0 + ar0) * lda + ak0;
        const bf16* a1 = A  + (size_t)(m0 + ar1) * lda + ak1;
        const bf16* b0 = Bw + (size_t)(n0 + ar0) * ldb + ak0;
        const bf16* b1 = Bw + (size_t)(n0 + ar1) * ldb + ak1;
        asm volatile("cp.async.cg.shared.global [%0],[%1],16;\n"::"r"(sa(&As[0][ar0][ak0])),"l"(a0));
        asm volatile("cp.async.cg.shared.global [%0],[%1],16;\n"::"r"(sa(&As[0][ar1][ak1])),"l"(a1));
        asm volatile("cp.async.cg.shared.global [%0],[%1],16;\n"::"r"(sa(&Bs[0][ar0][ak0])),"l"(b0));
        asm volatile("cp.async.cg.shared.global [%0],[%1],16;\n"::"r"(sa(&Bs[0][ar1][ak1])),"l"(b1));
        asm volatile("cp.async.commit_group;\n");
    }

    for (int kb = 0; kb < nK; kb++) {
        asm volatile("cp.async.wait_group 0;\n");
        __syncthreads();
        if (kb + 1 < nK) {
            int st = (kb + 1) & 1;
            int ko = (kb + 1) * 32;
            const bf16* a0 = A  + (size_t)(m0 + ar0) * lda + ko + ak0;
            const bf16* a1 = A  + (size_t)(m0 + ar1) * lda + ko + ak1;
            const bf16* b0 = Bw + (size_t)(n0 + ar0) * ldb + ko + ak0;
            const bf16* b1 = Bw + (size_t)(n0 + ar1) * ldb + ko + ak1;
            asm volatile("cp.async.cg.shared.global [%0],[%1],16;\n"::"r"(sa(&As[st][ar0][ak0])),"l"(a0));
            asm volatile("cp.async.cg.shared.global [%0],[%1],16;\n"::"r"(sa(&As[st][ar1][ak1])),"l"(a1));
            asm volatile("cp.async.cg.shared.global [%0],[%1],16;\n"::"r"(sa(&Bs[st][ar0][ak0])),"l"(b0));
            asm volatile("cp.async.cg.shared.global [%0],[%1],16;\n"::"r"(sa(&Bs[st][ar1][ak1])),"l"(b1));
            asm volatile("cp.async.commit_group;\n");
        }
        int st = kb & 1;
#pragma unroll
        for (int ks = 0; ks < 2; ks++) {
            unsigned a[4][4];
            unsigned bfr[4][2];
#pragma unroll
            for (int mt = 0; mt < 4; mt++) {
                unsigned ad = sa(&As[st][wm0 + mt*16 + (lane & 15)][ks*16 + (lane >> 4)*8]);
                asm volatile("ldmatrix.sync.aligned.m8n8.x4.shared.b16 {%0,%1,%2,%3},[%4];\n"
                    : "=r"(a[mt][0]), "=r"(a[mt][1]), "=r"(a[mt][2]), "=r"(a[mt][3]) : "r"(ad));
            }
#pragma unroll
            for (int bp = 0; bp < 2; bp++) {
                unsigned r0, r1, r2, r3;
                unsigned ad = sa(&Bs[st][wn0 + bp*16 + (lane & 15)][ks*16 + (lane >> 4)*8]);
                asm volatile("ldmatrix.sync.aligned.m8n8.x4.shared.b16 {%0,%1,%2,%3},[%4];\n"
                    : "=r"(r0), "=r"(r1), "=r"(r2), "=r"(r3) : "r"(ad));
                bfr[bp*2  ][0] = r0; bfr[bp*2  ][1] = r2;
                bfr[bp*2+1][0] = r1; bfr[bp*2+1][1] = r3;
            }
#pragma unroll
            for (int mt = 0; mt < 4; mt++)
#pragma unroll
                for (int nt = 0; nt < 4; nt++) {
                    asm volatile(
                        "mma.sync.aligned.m16n8k16.row.col.f32.bf16.bf16.f32 "
                        "{%0,%1,%2,%3},{%4,%5,%6,%7},{%8,%9},{%0,%1,%2,%3};\n"
                        : "+f"(acc[mt][nt][0]), "+f"(acc[mt][nt][1]),
                          "+f"(acc[mt][nt][2]), "+f"(acc[mt][nt][3])
                        : "r"(a[mt][0]), "r"(a[mt][1]), "r"(a[mt][2]), "r"(a[mt][3]),
                          "r"(bfr[nt][0]), "r"(bfr[nt][1]));
                }
        }
        __syncthreads();
    }

    // ---------------- epilogue ----------------
    const int er = lane >> 2;
    const int ec = (lane & 3) * 2;
#pragma unroll
    for (int mt = 0; mt < 4; mt++) {
        float rsum0 = 0.f, rsum1 = 0.f;
        const int m = m0 + wm0 + mt*16 + er;
        float iq0 = 0.f, iq1 = 0.f;
        if (EP == 1) { iq0 = invq[m]; iq1 = invq[m + 8]; }
#pragma unroll
        for (int nt = 0; nt < 4; nt++) {
            int n = n0 + wn0 + nt*8 + ec;
            float v0 = acc[mt][nt][0], v1 = acc[mt][nt][1];
            float v2 = acc[mt][nt][2], v3 = acc[mt][nt][3];
            if (EP == 1) {
                float ik0 = invk[n], ik1 = invk[n+1];
                v0 = expp(v0 * iq0 * ik0); v1 = expp(v1 * iq0 * ik1);
                v2 = expp(v2 * iq1 * ik0); v3 = expp(v3 * iq1 * ik1);
                rsum0 += v0 + v1; rsum1 += v2 + v3;
                *(__nv_bfloat162*)&outH[(size_t)m * ldc + n]     = __floats2bfloat162_rn(v0, v1);
                *(__nv_bfloat162*)&outH[(size_t)(m+8) * ldc + n] = __floats2bfloat162_rn(v2, v3);
                if (m == 0) { p0[n] = v0; p0[n+1] = v1; }
            } else if (EP == 0) {
                *(__nv_bfloat162*)&outH[(size_t)m * ldc + n]     = __floats2bfloat162_rn(v0, v1);
                *(__nv_bfloat162*)&outH[(size_t)(m+8) * ldc + n] = __floats2bfloat162_rn(v2, v3);
            } else if (EP == 2) {
                float b0v = bias[n], b1v = bias[n+1];
                v0 = fmaxf(v0 + b0v, 0.f); v1 = fmaxf(v1 + b1v, 0.f);
                v2 = fmaxf(v2 + b0v, 0.f); v3 = fmaxf(v3 + b1v, 0.f);
                __nv_bfloat162 h01 = __floats2bfloat162_rn(v0, v1);
                __nv_bfloat162 h23 = __floats2bfloat162_rn(v2, v3);
                float2 f01 = __bfloat1622float2(h01);
                float2 f23 = __bfloat1622float2(h23);
                __nv_bfloat162 l01 = __floats2bfloat162_rn(v0 - f01.x, v1 - f01.y);
                __nv_bfloat162 l23 = __floats2bfloat162_rn(v2 - f23.x, v3 - f23.y);
                *(__nv_bfloat162*)&outH[(size_t)m * ldc + n]            = h01;
                *(__nv_bfloat162*)&outH[(size_t)m * ldc + n + 1024]     = h01;
                *(__nv_bfloat162*)&outH[(size_t)m * ldc + n + 2048]     = l01;
                *(__nv_bfloat162*)&outH[(size_t)(m+8) * ldc + n]        = h23;
                *(__nv_bfloat162*)&outH[(size_t)(m+8) * ldc + n + 1024] = h23;
                *(__nv_bfloat162*)&outH[(size_t)(m+8) * ldc + n + 2048] = l23;
            } else {
                float b0v = bias[n], b1v = bias[n+1];
                *(float2*)&outF[(size_t)m * ldc + n]     = make_float2(v0 + b0v, v1 + b1v);
                *(float2*)&outF[(size_t)(m+8) * ldc + n] = make_float2(v2 + b0v, v3 + b1v);
            }
        }
        if (EP == 1) {
            rsum0 += __shfl_xor_sync(0xffffffffu, rsum0, 1);
            rsum0 += __shfl_xor_sync(0xffffffffu, rsum0, 2);
            rsum1 += __shfl_xor_sync(0xffffffffu, rsum1, 1);
            rsum1 += __shfl_xor_sync(0xffffffffu, rsum1, 2);
            if ((lane & 3) == 0) {
                atomicAdd(&rowsum[m], rsum0);
                atomicAdd(&rowsum[m + 8], rsum1);
            }
        }
    }
}

// ---------------- GEMM wrappers ----------------
// G^T / Mq / Mk: 256x256, K=1024, from transposed bf16 weights
__global__ void __launch_bounds__(256) k_gmat() {
    int z = blockIdx.z; int h = z / 3, t = z - h * 3;
    const bf16* A; const bf16* B; bf16* C;
    const bf16* wqt = g_WQT + (size_t)h * D_ * K_;
    const bf16* wkt = g_WKT + (size_t)h * D_ * K_;
    if (t == 0)      { A = wkt; B = wqt; C = g_GT + h * D_ * D_; }   // GT[j,i]=G[i,j]
    else if (t == 1) { A = wqt; B = wqt; C = g_Mq + h * D_ * D_; }
    else             { A = wkt; B = wkt; C = g_Mk + h * D_ * D_; }
    mma_core<0>(A, K_, B, K_, K_, blockIdx.y*128, blockIdx.x*128,
                nullptr, C, D_, nullptr, nullptr, nullptr, nullptr, nullptr);
}

// u = memb@GT^T, yq = memb@Mq, yk = srcb@Mk   (all M=SB, N=256, K=256)
__global__ void __launch_bounds__(256) k_abc() {
    int z = blockIdx.z; int h = z / 3, t = z - h * 3;
    const bf16* A = (t == 2) ? g_srcb : g_memb;
    const bf16* B = (t == 0 ? g_GT : (t == 1 ? g_Mq : g_Mk)) + h * D_ * D_;
    bf16* C = (t == 0 ? g_u : (t == 1 ? g_yq : g_yk)) + (size_t)h * SB_ * D_;
    mma_core<0>(A, D_, B, D_, D_, blockIdx.y*128, blockIdx.x*128,
                nullptr, C, D_, nullptr, nullptr, nullptr, nullptr, nullptr);
}

__global__ void __launch_bounds__(256) k_gram() {
    int z = blockIdx.z; int h = z >> 2, b = z & 3;
    const bf16* A  = g_u    + (size_t)h * SB_ * D_ + b * D_;   // row q stride B*D
    const bf16* Bm = g_srcb + b * D_;
    const float* iq = g_ssq + (h * B_ + b) * S_;
    const float* ik = g_ssk + (h * B_ + b) * S_;
    bf16* C = g_P + (size_t)z * S_ * S_;
    mma_core<1>(A, B_*D_, Bm, B_*D_, D_, blockIdx.y*128, blockIdx.x*128,
                nullptr, C, S_, nullptr, g_rowsum + z * S_, g_P0 + z * S_, iq, ik);
}

__global__ void __launch_bounds__(256) k_ffn1(const float* __restrict__ l1b) {
    mma_core<2>(g_xs, 3*D_, g_l1ws, 3*D_, 3*D_, blockIdx.y*128, blockIdx.x*128,
                nullptr, g_h1s, 3*FF_, l1b, nullptr, nullptr, nullptr, nullptr);
}

__global__ void __launch_bounds__(256) k_ffn2(const float* __restrict__ l2b) {
    mma_core<3>(g_h1s, 3*FF_, g_l2ws, 3*FF_, 3*FF_, blockIdx.y*128, blockIdx.x*128,
                g_ff, nullptr, D_, l2b, nullptr, nullptr, nullptr, nullptr);
}

// ---------------- elementwise / reduction kernels ----------------
#define CV0 (SB_*D_/4)
#define CV1 (2*CV0)
__global__ void k_cvt_all(const float* __restrict__ srcc, const float* __restrict__ mem) {
    int i = blockIdx.x * 256 + threadIdx.x;
    if (i >= CV1) return;
    const float* s; bf16* d; int off;
    if (i < CV0) { s = srcc; d = g_srcb; off = i; }
    else         { s = mem;  d = g_memb; off = i - CV0; }
    float4 v = ((const float4*)s)[off];
    ((__nv_bfloat162*)d)[off*2]   = __floats2bfloat162_rn(v.x, v.y);
    ((__nv_bfloat162*)d)[off*2+1] = __floats2bfloat162_rn(v.z, v.w);
}

// transpose WQ/WK [h][k][i] f32 -> [h][i][k] bf16
__global__ void k_tr(const float* __restrict__ WQ, const float* __restrict__ WK) {
    int t = blockIdx.x * 256 + threadIdx.x;       // NH*D*K total
    int k = t & (K_ - 1);
    int rest = t >> 10;
    int i = rest & (D_ - 1);
    int h = rest >> 8;
    size_t src = ((size_t)h * K_ + k) * D_ + i;
    g_WQT[t] = __float2bfloat16(WQ[src]);
    g_WKT[t] = __float2bfloat16(WK[src]);
}

__global__ void k_wsplit(const float* __restrict__ src, int which) {
    int len = which == 0 ? D_ : FF_;
    bf16* dst = which == 0 ? g_l1ws : g_l2ws;
    int i = blockIdx.x * 256 + threadIdx.x;
    int row = i / len, c = i % len;
    float v = src[i];
    bf16 hi = __float2bfloat16(v);
    bf16 lo = __float2bfloat16(v - __bfloat162float(hi));
    size_t base = (size_t)row * 3 * len;
    dst[base + c] = hi;
    dst[base + len + c] = lo;
    dst[base + 2*len + c] = hi;
}

__global__ void k_zero3() {
    int i = blockIdx.x * 256 + threadIdx.x;
    if (i < ZB_*S_) { g_rowsum[i] = 0.f; g_colsum[i] = 0.f; }
    if (i < ZB_*D_) { g_ctx[i] = 0.f; g_s2[i] = 0.f; }
    if (i < B_*D_)  g_src2[i] = 0.f;
}

// inv norms: one warp per row; ss = y·x (256 elems); writes 1/max(sqrt,eps)
__global__ void k_rowdot() {
    int gw = (blockIdx.x * 256 + threadIdx.x) >> 5;
    int lane = threadIdx.x & 31;
    int which = gw >= NH_*SB_;
    int r = which ? gw - NH_*SB_ : gw;
    int h = r >> 13;                 // SB_ = 8192
    int sb = r & (SB_ - 1);
    const bf16* y = (which ? g_yk : g_yq) + (size_t)r * D_;
    const bf16* x = (which ? g_srcb : g_memb) + (size_t)sb * D_;
    uint4 yv = *(const uint4*)(y + lane * 8);
    uint4 xv = *(const uint4*)(x + lane * 8);
    const __nv_bfloat162* yp = (const __nv_bfloat162*)&yv;
    const __nv_bfloat162* xp = (const __nv_bfloat162*)&xv;
    float s = 0.f;
#pragma unroll
    for (int i = 0; i < 4; i++) {
        float2 a = __bfloat1622float2(yp[i]);
        float2 b = __bfloat1622float2(xp[i]);
        s = fmaf(a.x, b.x, s);
        s = fmaf(a.y, b.y, s);
    }
#pragma unroll
    for (int o = 16; o > 0; o >>= 1) s += __shfl_xor_sync(0xffffffffu, s, o);
    if (lane == 0) {
        int b = sb & 3, ss = sb >> 2;
        float* dst = which ? g_ssk : g_ssq;
        dst[h * SB_ + b * S_ + ss] = 1.f / fmaxf(sqrtf(s), 1e-12f);
    }
}

__global__ void k_colsum() {
    __shared__ float sinv[128];
    int z = blockIdx.y, qb = blockIdx.z;
    int t = threadIdx.x;
    if (t < 128) sinv[t] = 1.f / g_rowsum[z*S_ + qb*128 + t];
    __syncthreads();
    int s = blockIdx.x * 256 + t;
    const bf16* P = g_P + (size_t)z*S_*S_ + (size_t)qb*128*S_ + s;
    float cs = 0.f;
#pragma unroll 4
    for (int q = 0; q < 128; q++)
        cs = fmaf(__bfloat162float(P[(size_t)q * S_]), sinv[q], cs);
    atomicAdd(&g_colsum[z*S_ + s], cs);
}

__global__ void k_aff0() {
    int i = blockIdx.x * 256 + threadIdx.x;
    int z = i >> 11;
    float a0 = g_P0[i] / g_rowsum[z*S_];
    g_aff0[i] = a0 / (1e-9f + g_colsum[i]);
}

__global__ void k_ctx(const float* __restrict__ srcc) {
    int z = blockIdx.y; int b = z & 3;
    int d = threadIdx.x;
    int s0 = blockIdx.x * 256;
    float acc = 0.f;
    for (int si = 0; si < 256; si++) {
        int s = s0 + si;
        acc = fmaf(g_aff0[z*S_ + s], srcc[((size_t)s*B_ + b)*D_ + d], acc);
    }
    atomicAdd(&g_ctx[z*D_ + d], acc);
}

// ---------------- per-head chain (parallel split) ----------------
__global__ void k_headA(const float* __restrict__ memory,
                        const float* __restrict__ WV, const float* __restrict__ Wt) {
    __shared__ float cx[256], tv[256];
    int z = blockIdx.x; int h = z >> 2, b = z & 3;
    int t = threadIdx.x;
    cx[t] = g_ctx[z*D_ + t];
    __syncthreads();
    const float* wv = WV + ((size_t)h*D_ + t) * D_;
    float o = 0.f;
#pragma unroll 4
    for (int d = 0; d < D_; d++) o = fmaf(wv[d], cx[d], o);
    tv[t] = memory[(size_t)b * D_ + t] - o;
    __syncthreads();
    const float* wt = Wt + ((size_t)h*D_ + t) * D_;
    float r = 0.f;
#pragma unroll 4
    for (int d = 0; d < D_; d++) r = fmaf(wt[d], tv[d], r);
    g_rus[z*D_ + t] = fmaxf(r, 0.f);
}

__global__ void k_headB(const float* __restrict__ e1w, const float* __restrict__ e1b) {
    __shared__ float rus[256];
    int z = blockIdx.x; int h = z >> 2; int j = blockIdx.y;
    int t = threadIdx.x;
    rus[t] = g_rus[z*D_ + t];
    __syncthreads();
    int kx = j * 256 + t;
    const float* w = e1w + ((size_t)h*K_ + kx) * D_;
    float v = e1b[h*K_ + kx];
#pragma unroll 4
    for (int d = 0; d < D_; d++) v = fmaf(w[d], rus[d], v);
    g_hm[z*K_ + kx] = fmaxf(v, 0.f);
}

__global__ void k_headC(const float* __restrict__ e2w) {
    __shared__ float hm[256];
    int z = blockIdx.x; int h = z >> 2; int j = blockIdx.y;
    int t = threadIdx.x;
    hm[t] = g_hm[z*K_ + j*256 + t];
    __syncthreads();
    const float* w2 = e2w + ((size_t)h*D_ + t) * K_ + j*256;
    float s = 0.f;
#pragma unroll 4
    for (int kx = 0; kx < 256; kx++) s = fmaf(w2[kx], hm[kx], s);
    atomicAdd(&g_s2[z*D_ + t], s);
}

__global__ void k_headD(const float* __restrict__ e2b,
                        const float* __restrict__ eg, const float* __restrict__ eb) {
    __shared__ float red[8];
    int z = blockIdx.x; int h = z >> 2;
    int t = threadIdx.x;
    float v = g_rus[z*D_ + t] + g_s2[z*D_ + t] + e2b[h*D_ + t];
    g_xh[z*D_ + t] = ln256(v, eg[h*D_ + t], eb[h*D_ + t], red);
}

__global__ void k_out0(const float* __restrict__ Wout) {
    __shared__ float cat[256];
    int b = blockIdx.x, j = blockIdx.y, d = threadIdx.x;
    cat[d] = g_xh[(j*B_ + b)*D_ + d];
    __syncthreads();
    const float* w = Wout + (size_t)d * 1024 + j * 256;
    float acc = 0.f;
#pragma unroll 4
    for (int c = 0; c < 256; c++) acc = fmaf(w[c], cat[c], acc);
    atomicAdd(&g_src2[b*D_ + d], acc);
}

__global__ void k_ln1(const float* __restrict__ memory,
                      const float* __restrict__ n1g, const float* __restrict__ n1b) {
    __shared__ float red[8];
    int sb = blockIdx.x; int b = sb & 3; int t = threadIdx.x;
    float v = memory[(size_t)sb*D_ + t] + g_src2[b*D_ + t];
    float x = ln256(v, n1g[t], n1b[t], red);
    g_x[(size_t)sb*D_ + t] = x;
    bf16 hi = __float2bfloat16(x);
    bf16 lo = __float2bfloat16(x - __bfloat162float(hi));
    size_t base = (size_t)sb * 3 * D_;
    g_xs[base + t] = hi;
    g_xs[base + D_ + t] = hi;
    g_xs[base + 2*D_ + t] = lo;
}

__global__ void k_ln3(const float* __restrict__ n3g, const float* __restrict__ n3b,
                      float* __restrict__ out) {
    __shared__ float red[8];
    int sb = blockIdx.x; int t = threadIdx.x;
    float v = g_x[(size_t)sb*D_ + t] + g_ff[(size_t)sb*D_ + t];
    out[(size_t)sb*D_ + t] = ln256(v, n3g[t], n3b[t], red);
}

// ---------------- launch ----------------
extern "C" void kernel_launch(void* const* d_in, const int* in_sizes, int n_in,
                              void* d_out, int out_size) {
    (void)in_sizes; (void)n_in; (void)out_size;
    const float* srcc   = (const float*)d_in[0];
    const float* memory = (const float*)d_in[1];
    const float* WK   = (const float*)d_in[2];
    const float* WQ   = (const float*)d_in[3];
    const float* WV   = (const float*)d_in[4];
    const float* Wt   = (const float*)d_in[5];
    const float* e1w  = (const float*)d_in[6];
    const float* e1b  = (const float*)d_in[7];
    const float* e2w  = (const float*)d_in[8];
    const float* e2b  = (const float*)d_in[9];
    const float* eg   = (const float*)d_in[10];
    const float* eb   = (const float*)d_in[11];
    const float* Wout = (const float*)d_in[12];
    const float* l1w  = (const float*)d_in[13];
    const float* l1b  = (const float*)d_in[14];
    const float* l2w  = (const float*)d_in[15];
    const float* l2b  = (const float*)d_in[16];
    const float* n1g  = (const float*)d_in[17];
    const float* n1b  = (const float*)d_in[18];
    const float* n3g  = (const float*)d_in[19];
    const float* n3b  = (const float*)d_in[20];
    float* out = (float*)d_out;

    k_zero3  <<<(ZB_*S_ + 255)/256, 256>>>();
    k_cvt_all<<<(CV1 + 255)/256, 256>>>(srcc, memory);
    k_tr     <<<NH_*D_*K_/256, 256>>>(WQ, WK);
    k_wsplit <<<FF_*D_/256, 256>>>(l1w, 0);
    k_wsplit <<<D_*FF_/256, 256>>>(l2w, 1);

    k_gmat  <<<dim3(2, 2, 3*NH_), 256>>>();
    k_abc   <<<dim3(2, SB_/128, 3*NH_), 256>>>();
    k_rowdot<<<2*NH_*SB_/8, 256>>>();
    k_gram  <<<dim3(S_/128, S_/128, ZB_), 256>>>();
    k_colsum<<<dim3(S_/256, ZB_, S_/128), 256>>>();
    k_aff0  <<<ZB_*S_/256, 256>>>();
    k_ctx   <<<dim3(S_/256, ZB_), 256>>>(srcc);
    k_headA <<<ZB_, 256>>>(memory, WV, Wt);
    k_headB <<<dim3(ZB_, 4), 256>>>(e1w, e1b);
    k_headC <<<dim3(ZB_, 4), 256>>>(e2w);
    k_headD <<<ZB_, 256>>>(e2b, eg, eb);
    k_out0  <<<dim3(B_, 4), 256>>>(Wout);
    k_ln1   <<<SB_, 256>>>(memory, n1g, n1b);
    k_ffn1  <<<dim3(FF_/128, SB_/128), 256>>>(l1b);
    k_ffn2  <<<dim3(D_/128, SB_/128), 256>>>(l2b);
    k_ln3   <<<SB_, 256>>>(n3g, n3b, out);
}

// round 15
// speedup vs baseline: 2.5170x; 1.0479x over previous
#include <cuda_runtime.h>
#include <cuda_bf16.h>
#include <cstdint>

typedef __nv_bfloat16 bf16;

#define S_  2048
#define B_  4
#define D_  256
#define NH_ 4
#define K_  1024
#define FF_ 1024
#define SB_ (S_*B_)
#define ZB_ (NH_*B_)

// ---------------- scratch ----------------
static __device__ __align__(16) bf16  g_u  [(size_t)NH_*SB_*D_];   // u = memory@G^T  [h][s*B+b][d]
static __device__ __align__(16) bf16  g_GT [NH_*D_*D_];
static __device__ __align__(16) bf16  g_Mq [NH_*D_*D_];
static __device__ __align__(16) bf16  g_Mk [NH_*D_*D_];
static __device__ __align__(16) bf16  g_WQT[NH_*D_*K_];            // WQ^T bf16 [h][i][k]
static __device__ __align__(16) bf16  g_WKT[NH_*D_*K_];
static __device__ __align__(16) bf16  g_P  [(size_t)ZB_*S_*S_];    // 128 MB exp(dot) bf16
static __device__ float g_P0 [ZB_*S_];                             // exact row q=0
static __device__ float g_ssq[NH_*SB_];   // sum dots -> inv norms [h][b*S+s]
static __device__ float g_ssk[NH_*SB_];
static __device__ float g_rowsum[ZB_*S_];
static __device__ float g_colsum[ZB_*S_];
static __device__ float g_ctx[ZB_*D_];
static __device__ float g_rus[ZB_*D_];
static __device__ float g_s2 [ZB_*D_];
static __device__ float g_src2[B_*D_];
static __device__ __align__(16) float g_x  [SB_*D_];
static __device__ __align__(16) float g_ff [SB_*D_];
// split-bf16 FFN operands
static __device__ __align__(16) bf16 g_xs  [(size_t)SB_*3*D_];
static __device__ __align__(16) bf16 g_h1s [(size_t)SB_*3*FF_];
static __device__ __align__(16) bf16 g_l1ws[(size_t)FF_*3*D_];
static __device__ __align__(16) bf16 g_l2ws[(size_t)D_*3*FF_];
// bf16 copies of inputs
static __device__ __align__(16) bf16 g_srcb[SB_*D_];
static __device__ __align__(16) bf16 g_memb[SB_*D_];

// ---------------- small helpers ----------------
__device__ __forceinline__ float blk_sum(float v, float* red, int nw) {
#pragma unroll
    for (int o = 16; o > 0; o >>= 1) v += __shfl_xor_sync(0xffffffffu, v, o);
    int w = threadIdx.x >> 5;
    if ((threadIdx.x & 31) == 0) red[w] = v;
    __syncthreads();
    float s = 0.f;
    for (int i = 0; i < nw; i++) s += red[i];
    __syncthreads();
    return s;
}
__device__ __forceinline__ float ln256(float v, float g, float b, float* red) {
    float mean = blk_sum(v, red, 8) * (1.f/256.f);
    float dv = v - mean;
    float var = blk_sum(dv*dv, red, 8) * (1.f/256.f);
    return dv * rsqrtf(var + 1e-5f) * g + b;
}
__device__ __forceinline__ unsigned sa(const void* p) {
    return (unsigned)__cvta_generic_to_shared(p);
}
// exp(x) for x in [-1.05, 1.05]: degree-9 Taylor
__device__ __forceinline__ float expp(float x) {
    float r = 2.7557319e-6f;
    r = fmaf(r, x, 2.4801587e-5f);
    r = fmaf(r, x, 1.9841270e-4f);
    r = fmaf(r, x, 1.3888889e-3f);
    r = fmaf(r, x, 8.3333333e-3f);
    r = fmaf(r, x, 4.1666667e-2f);
    r = fmaf(r, x, 1.6666667e-1f);
    r = fmaf(r, x, 0.5f);
    r = fmaf(r, x, 1.0f);
    r = fmaf(r, x, 1.0f);
    return r;
}

// ---------------- bf16 HMMA GEMM core ----------------
// EP: 0 bf16 raw, 1 scale(invq,invk)+exp->bf16 P + f32 row0 + rowsum atomics,
//     2 relu+bias -> split triple bf16, 3 bias -> f32,
//     5 row-dot: ss[(m&3)*S+(m>>2)] += sum_n acc*x[m,n]  (no output store)
template<int EP>
__device__ __forceinline__ void mma_core(
    const bf16* __restrict__ A, int lda,
    const bf16* __restrict__ Bw, int ldb,
    int Kd, int m0, int n0,
    float* __restrict__ outF, bf16* __restrict__ outH, int ldc,
    const float* __restrict__ bias, float* __restrict__ rowsum, float* __restrict__ p0,
    const float* __restrict__ invq, const float* __restrict__ invk,
    const bf16* __restrict__ xrow)
{
    __shared__ __align__(16) bf16 As[2][128][40];
    __shared__ __align__(16) bf16 Bs[2][128][40];

    const int tid  = threadIdx.x;
    const int lane = tid & 31;
    const int wid  = tid >> 5;
    const int wm0  = (wid & 1) * 64;
    const int wn0  = (wid >> 1) * 32;

    const int c0 = tid, c1 = tid + 256;
    const int ar0 = c0 >> 2, ak0 = (c0 & 3) * 8;
    const int ar1 = c1 >> 2, ak1 = (c1 & 3) * 8;

    float acc[4][4][4];
#pragma unroll
    for (int i = 0; i < 4; i++)
#pragma unroll
        for (int j = 0; j < 4; j++)
#pragma unroll
            for (int k = 0; k < 4; k++) acc[i][j][k] = 0.f;

    const int nK = Kd >> 5;

    {
        const bf16* a0 = A  + (size_t)(m0 + ar0) * lda + ak0;
        const bf16* a1 = A  + (size_t)(m0 + ar1) * lda + ak1;
        const bf16* b0 = Bw + (size_t)(n0 + ar0) * ldb + ak0;
        const bf16* b1 = Bw + (size_t)(n0 + ar1) * ldb + ak1;
        asm volatile("cp.async.cg.shared.global [%0],[%1],16;\n"::"r"(sa(&As[0][ar0][ak0])),"l"(a0));
        asm volatile("cp.async.cg.shared.global [%0],[%1],16;\n"::"r"(sa(&As[0][ar1][ak1])),"l"(a1));
        asm volatile("cp.async.cg.shared.global [%0],[%1],16;\n"::"r"(sa(&Bs[0][ar0][ak0])),"l"(b0));
        asm volatile("cp.async.cg.shared.global [%0],[%1],16;\n"::"r"(sa(&Bs[0][ar1][ak1])),"l"(b1));
        asm volatile("cp.async.commit_group;\n");
    }

    for (int kb = 0; kb < nK; kb++) {
        asm volatile("cp.async.wait_group 0;\n");
        __syncthreads();
        if (kb + 1 < nK) {
            int st = (kb + 1) & 1;
            int ko = (kb + 1) * 32;
            const bf16* a0 = A  + (size_t)(m0 + ar0) * lda + ko + ak0;
            const bf16* a1 = A  + (size_t)(m0 + ar1) * lda + ko + ak1;
            const bf16* b0 = Bw + (size_t)(n0 + ar0) * ldb + ko + ak0;
            const bf16* b1 = Bw + (size_t)(n0 + ar1) * ldb + ko + ak1;
            asm volatile("cp.async.cg.shared.global [%0],[%1],16;\n"::"r"(sa(&As[st][ar0][ak0])),"l"(a0));
            asm volatile("cp.async.cg.shared.global [%0],[%1],16;\n"::"r"(sa(&As[st][ar1][ak1])),"l"(a1));
            asm volatile("cp.async.cg.shared.global [%0],[%1],16;\n"::"r"(sa(&Bs[st][ar0][ak0])),"l"(b0));
            asm volatile("cp.async.cg.shared.global [%0],[%1],16;\n"::"r"(sa(&Bs[st][ar1][ak1])),"l"(b1));
            asm volatile("cp.async.commit_group;\n");
        }
        int st = kb & 1;
#pragma unroll
        for (int ks = 0; ks < 2; ks++) {
            unsigned a[4][4];
            unsigned bfr[4][2];
#pragma unroll
            for (int mt = 0; mt < 4; mt++) {
                unsigned ad = sa(&As[st][wm0 + mt*16 + (lane & 15)][ks*16 + (lane >> 4)*8]);
                asm volatile("ldmatrix.sync.aligned.m8n8.x4.shared.b16 {%0,%1,%2,%3},[%4];\n"
                    : "=r"(a[mt][0]), "=r"(a[mt][1]), "=r"(a[mt][2]), "=r"(a[mt][3]) : "r"(ad));
            }
#pragma unroll
            for (int bp = 0; bp < 2; bp++) {
                unsigned r0, r1, r2, r3;
                unsigned ad = sa(&Bs[st][wn0 + bp*16 + (lane & 15)][ks*16 + (lane >> 4)*8]);
                asm volatile("ldmatrix.sync.aligned.m8n8.x4.shared.b16 {%0,%1,%2,%3},[%4];\n"
                    : "=r"(r0), "=r"(r1), "=r"(r2), "=r"(r3) : "r"(ad));
                bfr[bp*2  ][0] = r0; bfr[bp*2  ][1] = r2;
                bfr[bp*2+1][0] = r1; bfr[bp*2+1][1] = r3;
            }
#pragma unroll
            for (int mt = 0; mt < 4; mt++)
#pragma unroll
                for (int nt = 0; nt < 4; nt++) {
                    asm volatile(
                        "mma.sync.aligned.m16n8k16.row.col.f32.bf16.bf16.f32 "
                        "{%0,%1,%2,%3},{%4,%5,%6,%7},{%8,%9},{%0,%1,%2,%3};\n"
                        : "+f"(acc[mt][nt][0]), "+f"(acc[mt][nt][1]),
                          "+f"(acc[mt][nt][2]), "+f"(acc[mt][nt][3])
                        : "r"(a[mt][0]), "r"(a[mt][1]), "r"(a[mt][2]), "r"(a[mt][3]),
                          "r"(bfr[nt][0]), "r"(bfr[nt][1]));
                }
        }
        __syncthreads();
    }

    // ---------------- epilogue ----------------
    const int er = lane >> 2;
    const int ec = (lane & 3) * 2;
#pragma unroll
    for (int mt = 0; mt < 4; mt++) {
        float rsum0 = 0.f, rsum1 = 0.f;
        const int m = m0 + wm0 + mt*16 + er;
        float iq0 = 0.f, iq1 = 0.f;
        if (EP == 1) { iq0 = invq[m]; iq1 = invq[m + 8]; }
#pragma unroll
        for (int nt = 0; nt < 4; nt++) {
            int n = n0 + wn0 + nt*8 + ec;
            float v0 = acc[mt][nt][0], v1 = acc[mt][nt][1];
            float v2 = acc[mt][nt][2], v3 = acc[mt][nt][3];
            if (EP == 1) {
                float ik0 = invk[n], ik1 = invk[n+1];
                v0 = expp(v0 * iq0 * ik0); v1 = expp(v1 * iq0 * ik1);
                v2 = expp(v2 * iq1 * ik0); v3 = expp(v3 * iq1 * ik1);
                rsum0 += v0 + v1; rsum1 += v2 + v3;
                *(__nv_bfloat162*)&outH[(size_t)m * ldc + n]     = __floats2bfloat162_rn(v0, v1);
                *(__nv_bfloat162*)&outH[(size_t)(m+8) * ldc + n] = __floats2bfloat162_rn(v2, v3);
                if (m == 0) { p0[n] = v0; p0[n+1] = v1; }
            } else if (EP == 0) {
                *(__nv_bfloat162*)&outH[(size_t)m * ldc + n]     = __floats2bfloat162_rn(v0, v1);
                *(__nv_bfloat162*)&outH[(size_t)(m+8) * ldc + n] = __floats2bfloat162_rn(v2, v3);
            } else if (EP == 5) {
                float2 f0 = __bfloat1622float2(*(const __nv_bfloat162*)&xrow[(size_t)m * D_ + n]);
                float2 f1 = __bfloat1622float2(*(const __nv_bfloat162*)&xrow[(size_t)(m+8) * D_ + n]);
                rsum0 = fmaf(v0, f0.x, fmaf(v1, f0.y, rsum0));
                rsum1 = fmaf(v2, f1.x, fmaf(v3, f1.y, rsum1));
            } else if (EP == 2) {
                float b0v = bias[n], b1v = bias[n+1];
                v0 = fmaxf(v0 + b0v, 0.f); v1 = fmaxf(v1 + b1v, 0.f);
                v2 = fmaxf(v2 + b0v, 0.f); v3 = fmaxf(v3 + b1v, 0.f);
                __nv_bfloat162 h01 = __floats2bfloat162_rn(v0, v1);
                __nv_bfloat162 h23 = __floats2bfloat162_rn(v2, v3);
                float2 f01 = __bfloat1622float2(h01);
                float2 f23 = __bfloat1622float2(h23);
                __nv_bfloat162 l01 = __floats2bfloat162_rn(v0 - f01.x, v1 - f01.y);
                __nv_bfloat162 l23 = __floats2bfloat162_rn(v2 - f23.x, v3 - f23.y);
                *(__nv_bfloat162*)&outH[(size_t)m * ldc + n]            = h01;
                *(__nv_bfloat162*)&outH[(size_t)m * ldc + n + 1024]     = h01;
                *(__nv_bfloat162*)&outH[(size_t)m * ldc + n + 2048]     = l01;
                *(__nv_bfloat162*)&outH[(size_t)(m+8) * ldc + n]        = h23;
                *(__nv_bfloat162*)&outH[(size_t)(m+8) * ldc + n + 1024] = h23;
                *(__nv_bfloat162*)&outH[(size_t)(m+8) * ldc + n + 2048] = l23;
            } else {
                float b0v = bias[n], b1v = bias[n+1];
                *(float2*)&outF[(size_t)m * ldc + n]     = make_float2(v0 + b0v, v1 + b1v);
                *(float2*)&outF[(size_t)(m+8) * ldc + n] = make_float2(v2 + b0v, v3 + b1v);
            }
        }
        if (EP == 1 || EP == 5) {
            rsum0 += __shfl_xor_sync(0xffffffffu, rsum0, 1);
            rsum0 += __shfl_xor_sync(0xffffffffu, rsum0, 2);
            rsum1 += __shfl_xor_sync(0xffffffffu, rsum1, 1);
            rsum1 += __shfl_xor_sync(0xffffffffu, rsum1, 2);
            if ((lane & 3) == 0) {
                if (EP == 1) {
                    atomicAdd(&rowsum[m], rsum0);
                    atomicAdd(&rowsum[m + 8], rsum1);
                } else {
                    atomicAdd(&rowsum[(m & 3) * S_ + (m >> 2)], rsum0);
                    atomicAdd(&rowsum[(m & 3) * S_ + (m >> 2) + 2], rsum1);
                }
            }
        }
    }
}

// ---------------- GEMM wrappers ----------------
__global__ void __launch_bounds__(256) k_gmat() {
    int z = blockIdx.z; int h = z / 3, t = z - h * 3;
    const bf16* A; const bf16* B; bf16* C;
    const bf16* wqt = g_WQT + (size_t)h * D_ * K_;
    const bf16* wkt = g_WKT + (size_t)h * D_ * K_;
    if (t == 0)      { A = wkt; B = wqt; C = g_GT + h * D_ * D_; }
    else if (t == 1) { A = wqt; B = wqt; C = g_Mq + h * D_ * D_; }
    else             { A = wkt; B = wkt; C = g_Mk + h * D_ * D_; }
    mma_core<0>(A, K_, B, K_, K_, blockIdx.y*128, blockIdx.x*128,
                nullptr, C, D_, nullptr, nullptr, nullptr, nullptr, nullptr, nullptr);
}

// t=0: u = memb@GT^T (store); t=1: ssq dot (memb@Mq)·memb; t=2: ssk dot (srcb@Mk)·srcb
__global__ void __launch_bounds__(256) k_abc() {
    int z = blockIdx.z; int h = z / 3, t = z - h * 3;
    if (t == 0) {
        mma_core<0>(g_memb, D_, g_GT + h * D_ * D_, D_, D_,
                    blockIdx.y*128, blockIdx.x*128,
                    nullptr, g_u + (size_t)h * SB_ * D_, D_,
                    nullptr, nullptr, nullptr, nullptr, nullptr, nullptr);
    } else if (t == 1) {
        mma_core<5>(g_memb, D_, g_Mq + h * D_ * D_, D_, D_,
                    blockIdx.y*128, blockIdx.x*128,
                    nullptr, nullptr, D_,
                    nullptr, g_ssq + h * SB_, nullptr, nullptr, nullptr, g_memb);
    } else {
        mma_core<5>(g_srcb, D_, g_Mk + h * D_ * D_, D_, D_,
                    blockIdx.y*128, blockIdx.x*128,
                    nullptr, nullptr, D_,
                    nullptr, g_ssk + h * SB_, nullptr, nullptr, nullptr, g_srcb);
    }
}

__global__ void __launch_bounds__(256) k_gram() {
    int z = blockIdx.z; int h = z >> 2, b = z & 3;
    const bf16* A  = g_u    + (size_t)h * SB_ * D_ + b * D_;
    const bf16* Bm = g_srcb + b * D_;
    const float* iq = g_ssq + (h * B_ + b) * S_;
    const float* ik = g_ssk + (h * B_ + b) * S_;
    bf16* C = g_P + (size_t)z * S_ * S_;
    mma_core<1>(A, B_*D_, Bm, B_*D_, D_, blockIdx.y*128, blockIdx.x*128,
                nullptr, C, S_, nullptr, g_rowsum + z * S_, g_P0 + z * S_, iq, ik, nullptr);
}

__global__ void __launch_bounds__(256) k_ffn1(const float* __restrict__ l1b) {
    mma_core<2>(g_xs, 3*D_, g_l1ws, 3*D_, 3*D_, blockIdx.y*128, blockIdx.x*128,
                nullptr, g_h1s, 3*FF_, l1b, nullptr, nullptr, nullptr, nullptr, nullptr);
}

__global__ void __launch_bounds__(256) k_ffn2(const float* __restrict__ l2b) {
    mma_core<3>(g_h1s, 3*FF_, g_l2ws, 3*FF_, 3*FF_, blockIdx.y*128, blockIdx.x*128,
                g_ff, nullptr, D_, l2b, nullptr, nullptr, nullptr, nullptr, nullptr);
}

// ---------------- fused preprocessing ----------------
// blocks: [0,128) zero | [128,4224) cvt | [4224,8320) tr | [8320,9344) wsplit1 | [9344,10368) wsplit2
#define PRE_Z  128
#define PRE_CV (PRE_Z + 4096)
#define PRE_TR (PRE_CV + 4096)
#define PRE_W1 (PRE_TR + 1024)
#define PRE_W2 (PRE_W1 + 1024)
__global__ void k_pre(const float* __restrict__ srcc, const float* __restrict__ mem,
                      const float* __restrict__ WQ, const float* __restrict__ WK,
                      const float* __restrict__ l1w, const float* __restrict__ l2w) {
    int blk = blockIdx.x, t = threadIdx.x;
    if (blk < PRE_Z) {
        int i = blk * 256 + t;
        g_rowsum[i] = 0.f; g_colsum[i] = 0.f;
        g_ssq[i] = 0.f;    g_ssk[i] = 0.f;
        if (i < ZB_*D_) { g_ctx[i] = 0.f; g_s2[i] = 0.f; }
        if (i < B_*D_)  g_src2[i] = 0.f;
    } else if (blk < PRE_CV) {
        int i = (blk - PRE_Z) * 256 + t;             // vec4 over 2*SB*D/4
        const float* s; bf16* d; int off;
        if (i < SB_*D_/4) { s = srcc; d = g_srcb; off = i; }
        else              { s = mem;  d = g_memb; off = i - SB_*D_/4; }
        float4 v = ((const float4*)s)[off];
        ((__nv_bfloat162*)d)[off*2]   = __floats2bfloat162_rn(v.x, v.y);
        ((__nv_bfloat162*)d)[off*2+1] = __floats2bfloat162_rn(v.z, v.w);
    } else if (blk < PRE_TR) {
        int i = (blk - PRE_CV) * 256 + t;            // NH*D*K
        int k = i & (K_ - 1);
        int rest = i >> 10;
        int ii = rest & (D_ - 1);
        int h = rest >> 8;
        size_t src = ((size_t)h * K_ + k) * D_ + ii;
        g_WQT[i] = __float2bfloat16(WQ[src]);
        g_WKT[i] = __float2bfloat16(WK[src]);
    } else {
        int which = blk < PRE_W1 ? 0 : 1;
        int i = (blk - (which ? PRE_W1 : PRE_TR)) * 256 + t;
        int len = which == 0 ? D_ : FF_;
        const float* src = which == 0 ? l1w : l2w;
        bf16* dst = which == 0 ? g_l1ws : g_l2ws;
        int row = i / len, c = i % len;
        float v = src[i];
        bf16 hi = __float2bfloat16(v);
        bf16 lo = __float2bfloat16(v - __bfloat162float(hi));
        size_t base = (size_t)row * 3 * len;
        dst[base + c] = hi;
        dst[base + len + c] = lo;
        dst[base + 2*len + c] = hi;
    }
}

// invn in place: 1/max(sqrt(ss),1e-12)
__global__ void k_invn() {
    int i = blockIdx.x * 256 + threadIdx.x;
    float* a = (i < NH_*SB_) ? g_ssq : g_ssk;
    int j = (i < NH_*SB_) ? i : i - NH_*SB_;
    a[j] = 1.f / fmaxf(sqrtf(a[j]), 1e-12f);
}

__global__ void k_colsum() {
    __shared__ float sinv[128];
    int z = blockIdx.y, qb = blockIdx.z;
    int t = threadIdx.x;
    if (t < 128) sinv[t] = 1.f / g_rowsum[z*S_ + qb*128 + t];
    __syncthreads();
    int s = blockIdx.x * 256 + t;
    const bf16* P = g_P + (size_t)z*S_*S_ + (size_t)qb*128*S_ + s;
    float cs = 0.f;
#pragma unroll 4
    for (int q = 0; q < 128; q++)
        cs = fmaf(__bfloat162float(P[(size_t)q * S_]), sinv[q], cs);
    atomicAdd(&g_colsum[z*S_ + s], cs);
}

// ctx with aff0 computed inline
__global__ void k_ctx(const float* __restrict__ srcc) {
    __shared__ float aff[256];
    int z = blockIdx.y; int b = z & 3;
    int t = threadIdx.x;
    int s0 = blockIdx.x * 256;
    {
        int s = s0 + t;
        float a0 = g_P0[z*S_ + s] / g_rowsum[z*S_];
        aff[t] = a0 / (1e-9f + g_colsum[z*S_ + s]);
    }
    __syncthreads();
    float acc = 0.f;
    for (int si = 0; si < 256; si++) {
        int s = s0 + si;
        acc = fmaf(aff[si], srcc[((size_t)s*B_ + b)*D_ + t], acc);
    }
    atomicAdd(&g_ctx[z*D_ + t], acc);
}

// ---------------- per-head chain ----------------
__global__ void k_headA(const float* __restrict__ memory,
                        const float* __restrict__ WV, const float* __restrict__ Wt) {
    __shared__ float cx[256], tv[256];
    int z = blockIdx.x; int h = z >> 2, b = z & 3;
    int t = threadIdx.x;
    cx[t] = g_ctx[z*D_ + t];
    __syncthreads();
    const float* wv = WV + ((size_t)h*D_ + t) * D_;
    float o = 0.f;
#pragma unroll 4
    for (int d = 0; d < D_; d++) o = fmaf(wv[d], cx[d], o);
    tv[t] = memory[(size_t)b * D_ + t] - o;
    __syncthreads();
    const float* wt = Wt + ((size_t)h*D_ + t) * D_;
    float r = 0.f;
#pragma unroll 4
    for (int d = 0; d < D_; d++) r = fmaf(wt[d], tv[d], r);
    g_rus[z*D_ + t] = fmaxf(r, 0.f);
}

// fused: hm chunk (smem) -> partial e2w dot (atomics)   grid (ZB_, 4)
__global__ void k_headBC(const float* __restrict__ e1w, const float* __restrict__ e1b,
                         const float* __restrict__ e2w) {
    __shared__ float rus[256], hm[256];
    int z = blockIdx.x; int h = z >> 2; int j = blockIdx.y;
    int t = threadIdx.x;
    rus[t] = g_rus[z*D_ + t];
    __syncthreads();
    int kx = j * 256 + t;
    const float* w = e1w + ((size_t)h*K_ + kx) * D_;
    float v = e1b[h*K_ + kx];
#pragma unroll 4
    for (int d = 0; d < D_; d++) v = fmaf(w[d], rus[d], v);
    hm[t] = fmaxf(v, 0.f);
    __syncthreads();
    const float* w2 = e2w + ((size_t)h*D_ + t) * K_ + j*256;
    float s = 0.f;
#pragma unroll 4
    for (int k2 = 0; k2 < 256; k2++) s = fmaf(w2[k2], hm[k2], s);
    atomicAdd(&g_s2[z*D_ + t], s);
}

// fused: LN(rus+s2+e2b) -> Wout partial dot   grid (B_, NH_)
__global__ void k_headDout(const float* __restrict__ e2b,
                           const float* __restrict__ eg, const float* __restrict__ eb,
                           const float* __restrict__ Wout) {
    __shared__ float xh[256], red[8];
    int b = blockIdx.x, h = blockIdx.y;
    int z = h * B_ + b;
    int t = threadIdx.x;
    float v = g_rus[z*D_ + t] + g_s2[z*D_ + t] + e2b[h*D_ + t];
    xh[t] = ln256(v, eg[h*D_ + t], eb[h*D_ + t], red);
    __syncthreads();
    const float* w = Wout + (size_t)t * 1024 + h * 256;
    float acc = 0.f;
#pragma unroll 4
    for (int c = 0; c < 256; c++) acc = fmaf(w[c], xh[c], acc);
    atomicAdd(&g_src2[b*D_ + t], acc);
}

__global__ void k_ln1(const float* __restrict__ memory,
                      const float* __restrict__ n1g, const float* __restrict__ n1b) {
    __shared__ float red[8];
    int sb = blockIdx.x; int b = sb & 3; int t = threadIdx.x;
    float v = memory[(size_t)sb*D_ + t] + g_src2[b*D_ + t];
    float x = ln256(v, n1g[t], n1b[t], red);
    g_x[(size_t)sb*D_ + t] = x;
    bf16 hi = __float2bfloat16(x);
    bf16 lo = __float2bfloat16(x - __bfloat162float(hi));
    size_t base = (size_t)sb * 3 * D_;
    g_xs[base + t] = hi;
    g_xs[base + D_ + t] = hi;
    g_xs[base + 2*D_ + t] = lo;
}

__global__ void k_ln3(const float* __restrict__ n3g, const float* __restrict__ n3b,
                      float* __restrict__ out) {
    __shared__ float red[8];
    int sb = blockIdx.x; int t = threadIdx.x;
    float v = g_x[(size_t)sb*D_ + t] + g_ff[(size_t)sb*D_ + t];
    out[(size_t)sb*D_ + t] = ln256(v, n3g[t], n3b[t], red);
}

// ---------------- launch ----------------
extern "C" void kernel_launch(void* const* d_in, const int* in_sizes, int n_in,
                              void* d_out, int out_size) {
    (void)in_sizes; (void)n_in; (void)out_size;
    const float* srcc   = (const float*)d_in[0];
    const float* memory = (const float*)d_in[1];
    const float* WK   = (const float*)d_in[2];
    const float* WQ   = (const float*)d_in[3];
    const float* WV   = (const float*)d_in[4];
    const float* Wt   = (const float*)d_in[5];
    const float* e1w  = (const float*)d_in[6];
    const float* e1b  = (const float*)d_in[7];
    const float* e2w  = (const float*)d_in[8];
    const float* e2b  = (const float*)d_in[9];
    const float* eg   = (const float*)d_in[10];
    const float* eb   = (const float*)d_in[11];
    const float* Wout = (const float*)d_in[12];
    const float* l1w  = (const float*)d_in[13];
    const float* l1b  = (const float*)d_in[14];
    const float* l2w  = (const float*)d_in[15];
    const float* l2b  = (const float*)d_in[16];
    const float* n1g  = (const float*)d_in[17];
    const float* n1b  = (const float*)d_in[18];
    const float* n3g  = (const float*)d_in[19];
    const float* n3b  = (const float*)d_in[20];
    float* out = (float*)d_out;

    k_pre     <<<PRE_W2, 256>>>(srcc, memory, WQ, WK, l1w, l2w);
    k_gmat    <<<dim3(2, 2, 3*NH_), 256>>>();
    k_abc     <<<dim3(2, SB_/128, 3*NH_), 256>>>();
    k_invn    <<<2*NH_*SB_/256, 256>>>();
    k_gram    <<<dim3(S_/128, S_/128, ZB_), 256>>>();
    k_colsum  <<<dim3(S_/256, ZB_, S_/128), 256>>>();
    k_ctx     <<<dim3(S_/256, ZB_), 256>>>(srcc);
    k_headA   <<<ZB_, 256>>>(memory, WV, Wt);
    k_headBC  <<<dim3(ZB_, 4), 256>>>(e1w, e1b, e2w);
    k_headDout<<<dim3(B_, NH_), 256>>>(e2b, eg, eb, Wout);
    k_ln1     <<<SB_, 256>>>(memory, n1g, n1b);
    k_ffn1    <<<dim3(FF_/128, SB_/128), 256>>>(l1b);
    k_ffn2    <<<dim3(D_/128, SB_/128), 256>>>(l2b);
    k_ln3     <<<SB_, 256>>>(n3g, n3b, out);
}